// round 13
// baseline (speedup 1.0000x reference)
#include <cuda_runtime.h>
#include <cuda_fp16.h>
#include <cstdint>
#include <math.h>

#define Bn   16
#define Ln   5000
#define Hn   256
#define Nn   32
#define NLn  4
#define DINn 12
#define Tc   128          // chunk length
#define Cc   40           // chunks (padded length 5120)
#define LP   5120         // padded L
#define Mrows (Bn * Cc)   // 640 chunk-rows

// ---------------- scratch (device globals; zero-initialized) ----------------
__device__ __align__(16) float  d_X  [(size_t)Bn * Ln * Hn];   // activations (B, L, H)
__device__ __align__(16) float  d_Zl [(size_t)Bn * Ln * Hn];   // LN output fp32 (B, L, H) residual
__device__ __align__(16) __half d_Ztr[(size_t)Bn * Hn * LP];   // LN output fp16 (B,H,Lpad), pad=0
__device__ __align__(16) __half d_Gt [(size_t)Bn * Hn * LP];   // fp16 gelu(y), (B, H, Lpad)
__device__ __align__(16) float4 d_SSMP[NLn * Hn * Nn];         // (lam_re, lam_im, 2Ct_re, 2Ct_im)
__device__ __align__(16) __half d_W2th[(size_t)NLn * 512 * Hn];// W_glu^T grouped rows, k-contig
__device__ __align__(16) float  d_b2t[NLn * 2 * Hn];
__device__ __align__(16) __half d_W1h[(size_t)NLn * Hn * 64 * 128]; // stage-1 B^T [n][k]
__device__ __align__(16) __half d_B3h[(size_t)NLn * Hn * 128 * 192];// stage-3 B^T [pos][k]
__device__ __align__(16) float  d_Kv[NLn * Hn * Tc];
__device__ __align__(16) float2 d_lamT[NLn * Hn * Nn];              // lambda^128

// ---------------- helpers ----------------
__device__ __forceinline__ void cp16h(__half* dst, const __half* src) {
    uint32_t d = (uint32_t)__cvta_generic_to_shared(dst);
    asm volatile("cp.async.cg.shared.global [%0], [%1], 16;\n" :: "r"(d), "l"(src));
}
__device__ __forceinline__ void cp_commit() {
    asm volatile("cp.async.commit_group;\n");
}
template <int N>
__device__ __forceinline__ void cp_wait() {
    asm volatile("cp.async.wait_group %0;\n" :: "n"(N));
}

__device__ __forceinline__ void mma_f16(float* d, const uint32_t* a, const uint32_t* b) {
    asm volatile(
        "mma.sync.aligned.m16n8k16.row.col.f32.f16.f16.f32 "
        "{%0,%1,%2,%3}, {%4,%5,%6,%7}, {%8,%9}, {%0,%1,%2,%3};\n"
        : "+f"(d[0]), "+f"(d[1]), "+f"(d[2]), "+f"(d[3])
        : "r"(a[0]), "r"(a[1]), "r"(a[2]), "r"(a[3]), "r"(b[0]), "r"(b[1]));
}

__device__ __forceinline__ void ldsm_x4(uint32_t* r, uint32_t addr) {
    asm volatile("ldmatrix.sync.aligned.m8n8.x4.shared.b16 {%0,%1,%2,%3}, [%4];"
        : "=r"(r[0]), "=r"(r[1]), "=r"(r[2]), "=r"(r[3]) : "r"(addr));
}
__device__ __forceinline__ void ldsm_x4_t(uint32_t* r, uint32_t addr) {
    asm volatile("ldmatrix.sync.aligned.m8n8.x4.trans.shared.b16 {%0,%1,%2,%3}, [%4];"
        : "=r"(r[0]), "=r"(r[1]), "=r"(r[2]), "=r"(r[3]) : "r"(addr));
}

__device__ __forceinline__ float gelu_fast(float x) {
    float t2 = 1.5957691216057308f * fmaf(0.044715f, x * x * x, x);
    return x * (1.f / (1.f + __expf(-t2)));
}

// ---------------- param prep ----------------
__global__ __launch_bounds__(256) void prep_ssm(
    const float* __restrict__ log_dt, const float* __restrict__ logA_re,
    const float* __restrict__ A_im,   const float* __restrict__ Cp)
{
    int idx = blockIdx.x * 256 + threadIdx.x;      // NL*H*N = 32768
    int i = idx / (Hn * Nn);
    int h = (idx / Nn) % Hn;
    float dt  = expf(log_dt[i * Hn + h]);
    float aRe = -expf(logA_re[idx]);
    float aIm = A_im[idx];
    float er  = expf(aRe * dt);
    float ang = aIm * dt;
    float lr = er * cosf(ang), li = er * sinf(ang);
    float nr = lr - 1.f, ni = li;
    float inv = 1.f / (aRe * aRe + aIm * aIm);
    float qr = (nr * aRe + ni * aIm) * inv;
    float qi = (ni * aRe - nr * aIm) * inv;
    float cr = Cp[2 * idx], ci = Cp[2 * idx + 1];
    float Ctr = cr * qr - ci * qi;
    float Cti = cr * qi + ci * qr;
    d_SSMP[idx] = make_float4(lr, li, 2.f * Ctr, 2.f * Cti);
}

__global__ __launch_bounds__(256) void prep_pow()
{
    int gw = blockIdx.x * 8 + (threadIdx.x >> 5);   // 0..1023 = layer*256+h
    int n  = threadIdx.x & 31;
    float4 p = d_SSMP[gw * 32 + n];
    float lr = p.x, li = p.y, tcr = p.z, tci = p.w;
    float curr = 1.f, curi = 0.f;
    __half* W1p = d_W1h + (size_t)gw * (64 * 128);
    __half* B3p = d_B3h + (size_t)gw * (128 * 192);
    float* Kvp = d_Kv + gw * Tc;
    for (int j = 0; j <= 128; j++) {
        if (j < 128) {
            float kr = tcr * curr - tci * curi;
            float ki = tcr * curi + tci * curr;
            W1p[n * 128 + (127 - j)]        = __float2half_rn(kr);
            W1p[(32 + n) * 128 + (127 - j)] = __float2half_rn(ki);
            float s = kr;
#pragma unroll
            for (int o = 16; o; o >>= 1) s += __shfl_xor_sync(0xffffffffu, s, o);
            if (n == 0) Kvp[j] = s;
        }
        if (j >= 1) {
            int i = j - 1;
            B3p[i * 192 + 128 + n] = __float2half_rn(curr);
            B3p[i * 192 + 160 + n] = __float2half_rn(-curi);
        }
        if (j == 128) d_lamT[gw * 32 + n] = make_float2(curr, curi);
        float nr2 = curr * lr - curi * li;
        curi = curr * li + curi * lr;
        curr = nr2;
    }
}

__global__ __launch_bounds__(128) void prep_tk(const float* __restrict__ Dp)
{
    int gw = blockIdx.x;
    int i  = threadIdx.x;
    __shared__ float Ks[Tc];
    Ks[i] = d_Kv[gw * Tc + i];
    __syncthreads();
    float Dh = Dp[gw];
    __half* B3p = d_B3h + (size_t)gw * (128 * 192);
    for (int j = 0; j < 128; j++) {
        float v = 0.f;
        if (i >= j) v = Ks[i - j] + (i == j ? Dh : 0.f);
        B3p[i * 192 + j] = __float2half_rn(v);
    }
}

__global__ __launch_bounds__(256) void prep_w2t(
    const float* __restrict__ W_glu, const float* __restrict__ b_glu)
{
    int idx = blockIdx.x * 256 + threadIdx.x;      // NL*512*256 = 524288
    int l = idx >> 17;
    int rem = idx & 131071;
    int row = rem >> 8;
    int k = rem & 255;
    int tile = row >> 7;
    int rr = row & 127;
    int col = (rr < 64) ? (tile * 64 + rr) : (Hn + tile * 64 + (rr - 64));
    d_W2th[idx] = __float2half_rn(W_glu[((size_t)l * Hn + k) * (2 * Hn) + col]);
    if (idx < NLn * 512) {
        int l2 = idx >> 9, row2 = idx & 511;
        int t2 = row2 >> 7, r2 = row2 & 127;
        int c2 = (r2 < 64) ? (t2 * 64 + r2) : (Hn + t2 * 64 + (r2 - 64));
        d_b2t[idx] = b_glu[l2 * 512 + c2];
    }
}

// ---------------- input projection ----------------
__global__ __launch_bounds__(256) void in_proj(
    const float* __restrict__ x, const float* __restrict__ W, const float* __restrict__ bias)
{
    __shared__ float xs[32][DINn];
    int tid = threadIdx.x;
    int r0 = blockIdx.x * 32;
    for (int t = tid; t < 32 * DINn; t += 256)
        xs[t / DINn][t % DINn] = x[(size_t)r0 * DINn + t];
    float w[DINn];
#pragma unroll
    for (int k = 0; k < DINn; k++) w[k] = W[k * Hn + tid];
    float bv = bias[tid];
    __syncthreads();
#pragma unroll 4
    for (int r = 0; r < 32; r++) {
        float a = bv;
#pragma unroll
        for (int k = 0; k < DINn; k++) a = fmaf(xs[r][k], w[k], a);
        d_X[((size_t)(r0 + r)) * Hn + tid] = a;
    }
}

// ---- LayerNorm: Ztr (fp16 transposed, GEMM A) + Zl (fp32 straight, residual) ----
__global__ __launch_bounds__(256) void ln_t_kernel(
    int layer, const float* __restrict__ ln_g, const float* __restrict__ ln_b)
{
    __shared__ float tile[32][257];
    __shared__ float mu[32], sc[32];
    int b  = blockIdx.y;
    int l0 = blockIdx.x * 32;
    int tid = threadIdx.x, lane = tid & 31, wid = tid >> 5;
    const float* Xb = d_X + (size_t)b * Ln * Hn;
#pragma unroll
    for (int r = 0; r < 32; r++) {
        int l = l0 + r;
        tile[r][tid] = (l < Ln) ? Xb[(size_t)l * Hn + tid] : 0.f;
    }
    __syncthreads();
#pragma unroll
    for (int rr = 0; rr < 4; rr++) {
        int r = wid * 4 + rr;
        float s = 0.f, q = 0.f;
#pragma unroll
        for (int k = 0; k < 8; k++) {
            float v = tile[r][k * 32 + lane];
            s += v; q += v * v;
        }
#pragma unroll
        for (int o = 16; o; o >>= 1) {
            s += __shfl_xor_sync(0xffffffffu, s, o);
            q += __shfl_xor_sync(0xffffffffu, q, o);
        }
        if (lane == 0) {
            float m = s * (1.f / 256.f);
            float v = q * (1.f / 256.f) - m * m;
            mu[r] = m;
            sc[r] = rsqrtf(v + 1e-5f);
        }
    }
    __syncthreads();
    const float* g  = ln_g + layer * Hn;
    const float* bb = ln_b + layer * Hn;
    float gh = g[tid], bh = bb[tid];
    float* Zlb = d_Zl + (size_t)b * Ln * Hn;
#pragma unroll 4
    for (int r = 0; r < 32; r++) {
        int l = l0 + r;
        if (l < Ln)
            Zlb[(size_t)l * Hn + tid] = (tile[r][tid] - mu[r]) * sc[r] * gh + bh;
    }
    __half* Zrb = d_Ztr + (size_t)b * Hn * LP;
    int l = l0 + lane;
    if (l < Ln) {
        float m = mu[lane], s = sc[lane];
#pragma unroll
        for (int hi = 0; hi < 32; hi++) {
            int h = wid * 32 + hi;
            float zv = (tile[lane][h] - m) * s * g[h] + bb[h];
            Zrb[(size_t)h * LP + l] = __float2half_rn(zv);
        }
    }
}

// ======== FUSED SSM: st1 GEMM + chunk scan + st3 GEMM, one block per (b,h) =========
// smem (halves): U[48][136] @0 ; Ws[64][136] @6528 (reused as Gt stage [48][136]);
// Bs[128][200] @15232 ; Ps[48][72] @40832 ; Qs(float)[48][68] @44288h (=177152B? no:
// byte off 88576). Total 101632 B.
__global__ __launch_bounds__(256) void ssm_fused(int layer)
{
    extern __shared__ __half smh[];
    __half* U  = smh;                 // [48][136]
    __half* Ws = smh + 6528;          // [64][136] W1 -> later output stage [48][136]
    __half* Bs = smh + 15232;         // [128][200]
    __half* Ps = smh + 40832;         // [48][72]
    float*  Qs = (float*)(smh + 44288); // [48][68]
    uint32_t sbase;
    asm("{ .reg .u64 t; cvta.to.shared.u64 t, %1; cvt.u32.u64 %0, t; }" : "=r"(sbase) : "l"(smh));
    const int b = blockIdx.x, h = blockIdx.y;
    int tid = threadIdx.x, lane = tid & 31, wid = tid >> 5;
    int tg = lane & 3, gp = lane >> 2;
    int grp = lane >> 3, lr = lane & 7;

    // ---- loads: U (40 rows), W1 (64 rows), B3 (128 rows) ----
    const __half* Usrc = d_Ztr + ((size_t)(b * Hn + h)) * LP;
    for (int idx = tid; idx < 640; idx += 256) {        // 40 rows x 16 granules
        int c = idx >> 4, g = idx & 15;
        cp16h(U + c * 136 + g * 8, Usrc + c * 128 + g * 8);
    }
    const __half* W1p = d_W1h + (size_t)(layer * Hn + h) * (64 * 128);
    for (int idx = tid; idx < 1024; idx += 256) {       // 64 rows x 16 granules
        int r = idx >> 4, g = idx & 15;
        cp16h(Ws + r * 136 + g * 8, W1p + r * 128 + g * 8);
    }
    const __half* B3p = d_B3h + (size_t)(layer * Hn + h) * (128 * 192);
    for (int idx = tid; idx < 3072; idx += 256) {       // 128 rows x 24 granules
        int r = idx / 24, g = idx - r * 24;
        cp16h(Bs + r * 200 + g * 8, B3p + r * 192 + g * 8);
    }
    // zero-fill U rows 40..47 and Ps rows 40..47 (pad rows; outputs discarded)
    for (int idx = tid; idx < 8 * 136; idx += 256)
        U[(40 + idx / 136) * 136 + (idx % 136)] = __float2half_rn(0.f);
    for (int idx = tid; idx < 8 * 72; idx += 256)
        Ps[(40 + idx / 72) * 72 + (idx % 72)] = __float2half_rn(0.f);
    cp_commit();
    cp_wait<0>();
    __syncthreads();

    // ---- st1: Q[48 x 64] = U[48 x 128] @ W1^T ; warp wid -> cols [wid*8, wid*8+8) --
    uint32_t aOffU = (uint32_t)((((grp & 1) * 8 + lr) * 136 + (grp >> 1) * 8) * 2);
    {
        float acc1[3][4] = {};
#pragma unroll
        for (int k2 = 0; k2 < 128; k2 += 16) {
            uint32_t af[3][4];
#pragma unroll
            for (int mi = 0; mi < 3; mi++)
                ldsm_x4(af[mi], sbase + aOffU + (uint32_t)((mi * 16 * 136 + k2) * 2));
            uint32_t bf[2];
            bf[0] = *(const uint32_t*)&Ws[(wid * 8 + gp) * 136 + k2 + tg * 2];
            bf[1] = *(const uint32_t*)&Ws[(wid * 8 + gp) * 136 + k2 + 8 + tg * 2];
#pragma unroll
            for (int mi = 0; mi < 3; mi++)
                mma_f16(acc1[mi], af[mi], bf);
        }
#pragma unroll
        for (int mi = 0; mi < 3; mi++) {
            int col = wid * 8 + tg * 2;
            Qs[(mi * 16 + gp) * 68 + col]     = acc1[mi][0];
            Qs[(mi * 16 + gp) * 68 + col + 1] = acc1[mi][1];
            Qs[(mi * 16 + gp + 8) * 68 + col]     = acc1[mi][2];
            Qs[(mi * 16 + gp + 8) * 68 + col + 1] = acc1[mi][3];
        }
    }
    __syncthreads();

    // ---- st2: serial scan over 40 chunks (warp 0) ----
    if (tid < 32) {
        float2 lt = d_lamT[(layer * Hn + h) * 32 + tid];
        float pr = 0.f, pi = 0.f;
        for (int c = 0; c < Cc; c++) {
            Ps[c * 72 + tid]      = __float2half_rn(pr);
            Ps[c * 72 + 32 + tid] = __float2half_rn(pi);
            float qr = Qs[c * 68 + tid], qi = Qs[c * 68 + 32 + tid];
            float prn = fmaf(lt.x, pr, fmaf(-lt.y, pi, qr));
            pi        = fmaf(lt.y, pr, fmaf( lt.x, pi, qi));
            pr = prn;
        }
    }
    __syncthreads();

    // ---- st3: Y[48 x 128] = [U | P][48 x 192] @ B3^T ; warp -> cols [wid*16,+16) ---
    float acc3[3][2][4] = {};
    uint32_t aOffP = (uint32_t)((40832 + ((grp & 1) * 8 + lr) * 72 + (grp >> 1) * 8) * 2);
    uint32_t bOffB = (uint32_t)((15232 + (wid * 16 + (grp & 1) * 8 + lr) * 200 + (grp >> 1) * 8) * 2);
#pragma unroll
    for (int k2 = 0; k2 < 192; k2 += 16) {
        uint32_t af[3][4];
        if (k2 < 128) {
#pragma unroll
            for (int mi = 0; mi < 3; mi++)
                ldsm_x4(af[mi], sbase + aOffU + (uint32_t)((mi * 16 * 136 + k2) * 2));
        } else {
#pragma unroll
            for (int mi = 0; mi < 3; mi++)
                ldsm_x4(af[mi], sbase + aOffP + (uint32_t)((mi * 16 * 72 + (k2 - 128)) * 2));
        }
        uint32_t q[4], bf[2][2];
        ldsm_x4(q, sbase + bOffB + (uint32_t)(k2 * 2));
        bf[0][0] = q[0]; bf[1][0] = q[1];
        bf[0][1] = q[2]; bf[1][1] = q[3];
#pragma unroll
        for (int mi = 0; mi < 3; mi++)
#pragma unroll
            for (int ni = 0; ni < 2; ni++)
                mma_f16(acc3[mi][ni], af[mi], bf[ni]);
    }
    __syncthreads();   // done reading Ws (W1) and U; Ws reused as output stage

    // stage gelu(Y) rows<48 in Ws [48][136]
#pragma unroll
    for (int mi = 0; mi < 3; mi++) {
#pragma unroll
        for (int ni = 0; ni < 2; ni++) {
            int col = wid * 16 + ni * 8 + tg * 2;
#pragma unroll
            for (int hf = 0; hf < 2; hf++) {
                int row = mi * 16 + gp + hf * 8;
                __half2 v = __floats2half2_rn(gelu_fast(acc3[mi][ni][hf * 2]),
                                              gelu_fast(acc3[mi][ni][hf * 2 + 1]));
                *(__half2*)&Ws[row * 136 + col] = v;
            }
        }
    }
    __syncthreads();
    // coalesced store rows 0..39 -> Gt
    __half* Gdst = d_Gt + ((size_t)(b * Hn + h)) * LP;
    for (int idx = tid; idx < 640; idx += 256) {
        int c = idx >> 4, g = idx & 15;
        *(uint4*)(Gdst + c * 128 + g * 8) = *(const uint4*)&Ws[c * 136 + g * 8];
    }
}

// -------- GLU GEMM fp16 (ldmatrix, direct Gt): D[ch 128][l 128] = W2t x Gt^T --------
__global__ __launch_bounds__(256) void glu_kernel(int layer)
{
    extern __shared__ __half smh[];
    __shared__ float biasS[128];
    uint32_t sbase;
    asm("{ .reg .u64 t; cvta.to.shared.u64 t, %1; cvt.u32.u64 %0, t; }" : "=r"(sbase) : "l"(smh));
    const int tile = blockIdx.x;           // channel group 0..3
    const int l0   = blockIdx.y * 128;
    const int b    = blockIdx.z;
    const int m0   = tile * 128;
    int tid = threadIdx.x, lane = tid & 31, wid = tid >> 5;
    int wm = wid & 3, wn = wid >> 2;       // warp tile: 32 m x 64 n
    int tg = lane & 3, gp = lane >> 2;

    if (tid < 128) biasS[tid] = d_b2t[layer * 512 + m0 + tid];

    int rA = tid >> 1, gA = (tid & 1) * 2;
    const __half* Wp = d_W2th + (size_t)(layer * 512 + m0 + rA) * 256;
    int rB = tid >> 3, gB = tid & 7;       // B: 32 k-rows x 16 granules, 2 per thread
    const __half* Gp = d_Gt + ((size_t)(b * Hn + rB)) * LP + l0;

    float acc[2][8][4] = {};

    auto fill = [&](int s) {
        int kt = s * 32;
        __half* dA = smh + (s % 3) * (128 * 40);
        cp16h(dA + rA * 40 + gA * 8, Wp + kt + gA * 8);
        cp16h(dA + rA * 40 + (gA + 1) * 8, Wp + kt + (gA + 1) * 8);
        __half* dB = smh + 15360 + (s % 3) * (32 * 136);
        const __half* src = Gp + (size_t)kt * LP;
        cp16h(dB + rB * 136 + gB * 8, src + gB * 8);
        cp16h(dB + rB * 136 + (gB + 8) * 8, src + (gB + 8) * 8);
    };

    int grp = lane >> 3, lr = lane & 7;
    uint32_t aOff = (uint32_t)(((wm * 32 + (grp & 1) * 8 + lr) * 40 + (grp >> 1) * 8) * 2);
    uint32_t bOff = (uint32_t)((((grp & 1) * 8 + lr) * 136 + wn * 64 + (grp >> 1) * 8) * 2);

    fill(0); cp_commit();
    fill(1); cp_commit();
#pragma unroll
    for (int s = 0; s < 8; s++) {
        if (s < 7) cp_wait<1>(); else cp_wait<0>();
        __syncthreads();
        if (s + 2 < 8) { fill(s + 2); cp_commit(); }
        uint32_t aBuf = sbase + (uint32_t)((s % 3) * (128 * 40) * 2);
        uint32_t bBuf = sbase + (uint32_t)((15360 + (s % 3) * (32 * 136)) * 2);
#pragma unroll
        for (int k2 = 0; k2 < 32; k2 += 16) {
            uint32_t af[2][4], bf[8][2];
#pragma unroll
            for (int mi = 0; mi < 2; mi++)
                ldsm_x4(af[mi], aBuf + aOff + (uint32_t)((mi * 16 * 40 + k2) * 2));
#pragma unroll
            for (int nj = 0; nj < 4; nj++) {
                uint32_t q[4];
                ldsm_x4_t(q, bBuf + bOff + (uint32_t)((k2 * 136 + nj * 16) * 2));
                bf[nj * 2][0] = q[0]; bf[nj * 2][1] = q[1];
                bf[nj * 2 + 1][0] = q[2]; bf[nj * 2 + 1][1] = q[3];
            }
#pragma unroll
            for (int mi = 0; mi < 2; mi++)
#pragma unroll
                for (int ni = 0; ni < 8; ni++)
                    mma_f16(acc[mi][ni], af[mi], bf[ni]);
        }
    }

    // stage C[ch][l] (+bias) in fp32, then GLU + Zl residual, coalesced X writes
    __syncthreads();
    float* stgF = (float*)smh;             // [128 ch][133 l]
#pragma unroll
    for (int mi = 0; mi < 2; mi++) {
#pragma unroll
        for (int hf = 0; hf < 2; hf++) {
            int row = wm * 32 + mi * 16 + gp + hf * 8;
            float bv = biasS[row];
#pragma unroll
            for (int ni = 0; ni < 8; ni++) {
                int col = wn * 64 + ni * 8 + tg * 2;
                stgF[row * 133 + col]     = acc[mi][ni][hf * 2]     + bv;
                stgF[row * 133 + col + 1] = acc[mi][ni][hf * 2 + 1] + bv;
            }
        }
    }
    __syncthreads();
#pragma unroll
    for (int it = 0; it < 8; it++) {
        int idx = tid + it * 256;          // 2048 tasks = 128 l-rows x 16 float4
        int row_l = idx >> 4;
        int j = (idx & 15) * 4;            // channel within 64
        int gl = l0 + row_l;
        if (gl < Ln) {
            const float* Zp = d_Zl + ((size_t)b * Ln + gl) * Hn + tile * 64;
            float* Xp = d_X + ((size_t)b * Ln + gl) * Hn + tile * 64;
            float a0 = stgF[(j    ) * 133 + row_l], g0 = stgF[(64 + j    ) * 133 + row_l];
            float a1 = stgF[(j + 1) * 133 + row_l], g1 = stgF[(65 + j    ) * 133 + row_l];
            float a2 = stgF[(j + 2) * 133 + row_l], g2 = stgF[(66 + j    ) * 133 + row_l];
            float a3 = stgF[(j + 3) * 133 + row_l], g3 = stgF[(67 + j    ) * 133 + row_l];
            float4 o, z;
            o.x = a0 * (1.f / (1.f + __expf(-g0)));
            o.y = a1 * (1.f / (1.f + __expf(-g1)));
            o.z = a2 * (1.f / (1.f + __expf(-g2)));
            o.w = a3 * (1.f / (1.f + __expf(-g3)));
            z = *(const float4*)(Zp + j);
            o.x += z.x; o.y += z.y; o.z += z.z; o.w += z.w;
            *(float4*)(Xp + j) = o;
        }
    }
}

// ---------------- final LayerNorm -> d_out ----------------
__global__ __launch_bounds__(256) void final_ln(
    const float* __restrict__ g, const float* __restrict__ bb, float* __restrict__ out)
{
    int lane = threadIdx.x & 31, wid = threadIdx.x >> 5;
    size_t row = (size_t)blockIdx.x * 8 + wid;
    const float* xr = d_X + row * Hn;
    float v[8], s = 0.f, q = 0.f;
#pragma unroll
    for (int k = 0; k < 8; k++) {
        v[k] = xr[k * 32 + lane];
        s += v[k]; q += v[k] * v[k];
    }
#pragma unroll
    for (int o = 16; o; o >>= 1) {
        s += __shfl_xor_sync(0xffffffffu, s, o);
        q += __shfl_xor_sync(0xffffffffu, q, o);
    }
    float m  = s * (1.f / 256.f);
    float sc = rsqrtf(q * (1.f / 256.f) - m * m + 1e-5f);
#pragma unroll
    for (int k = 0; k < 8; k++) {
        int h = k * 32 + lane;
        out[row * Hn + h] = (v[k] - m) * sc * g[h] + bb[h];
    }
}

// ---------------- launch ----------------
extern "C" void kernel_launch(void* const* d_in, const int* in_sizes, int n_in,
                              void* d_out, int out_size)
{
    const float* x       = (const float*)d_in[0];
    const float* W_in    = (const float*)d_in[1];
    const float* b_in    = (const float*)d_in[2];
    const float* ln_g    = (const float*)d_in[3];
    const float* ln_b    = (const float*)d_in[4];
    const float* log_dt  = (const float*)d_in[5];
    const float* logA_re = (const float*)d_in[6];
    const float* A_im    = (const float*)d_in[7];
    const float* Cp      = (const float*)d_in[8];
    const float* Dp      = (const float*)d_in[9];
    const float* W_glu   = (const float*)d_in[10];
    const float* b_glu   = (const float*)d_in[11];
    const float* fn_g    = (const float*)d_in[12];
    const float* fn_b    = (const float*)d_in[13];
    float* out = (float*)d_out;

    const int smem_ssm = 44288 * 2 + 48 * 68 * 4;             // 101632
    const int smem_glu = 128 * 133 * 4;                       // 68096 (>= mainloop 56832)
    cudaFuncSetAttribute(ssm_fused, cudaFuncAttributeMaxDynamicSharedMemorySize, smem_ssm);
    cudaFuncSetAttribute(glu_kernel, cudaFuncAttributeMaxDynamicSharedMemorySize, smem_glu);

    prep_ssm<<<128, 256>>>(log_dt, logA_re, A_im, Cp);
    prep_pow<<<128, 256>>>();
    prep_tk<<<NLn * Hn, 128>>>(Dp);
    prep_w2t<<<2048, 256>>>(W_glu, b_glu);
    in_proj<<<2500, 256>>>(x, W_in, b_in);

    for (int i = 0; i < NLn; i++) {
        dim3 gln((Ln + 31) / 32, Bn);
        ln_t_kernel<<<gln, 256>>>(i, ln_g, ln_b);
        ssm_fused<<<dim3(Bn, Hn), 256, smem_ssm>>>(i);
        glu_kernel<<<dim3(4, LP / 128, Bn), 256, smem_glu>>>(i);
    }
    final_ln<<<(Bn * Ln) / 8, 256>>>(fn_g, fn_b, out);
}

// round 14
// speedup vs baseline: 1.0439x; 1.0439x over previous
#include <cuda_runtime.h>
#include <cuda_fp16.h>
#include <cstdint>
#include <math.h>

#define Bn   16
#define Ln   5000
#define Hn   256
#define Nn   32
#define NLn  4
#define DINn 12
#define Tc   128          // chunk length
#define Cc   40           // chunks (padded length 5120)
#define LP   5120         // padded L
#define Mrows (Bn * Cc)   // 640 chunk-rows

// ---------------- scratch (device globals; zero-initialized) ----------------
__device__ __align__(16) float  d_X  [(size_t)Bn * Ln * Hn];   // activations (B, L, H)
__device__ __align__(16) float  d_Zl [(size_t)Bn * Ln * Hn];   // LN output fp32 (B, L, H) residual
__device__ __align__(16) __half d_Ztr[(size_t)Bn * Hn * LP];   // LN output fp16 (B,H,Lpad), pad=0
__device__ __align__(16) __half d_Gt [(size_t)Bn * Hn * LP];   // fp16 gelu(y), (B, H, Lpad)
__device__ __align__(16) float4 d_SSMP[NLn * Hn * Nn];         // (lam_re, lam_im, 2Ct_re, 2Ct_im)
__device__ __align__(16) __half d_W2th[(size_t)NLn * 512 * Hn];// W_glu^T grouped rows, k-contig
__device__ __align__(16) float  d_b2t[NLn * 2 * Hn];
__device__ __align__(16) float  d_Q   [(size_t)Bn * Hn * Cc * 64];  // chunk state contributions
__device__ __align__(16) __half d_Pt2h[(size_t)Hn * Mrows * 64];    // fp16 chunk-start states
__device__ __align__(16) __half d_W1h[(size_t)NLn * Hn * 64 * 128]; // stage-1 B^T [n][k]
__device__ __align__(16) __half d_B3h[(size_t)NLn * Hn * 128 * 192];// stage-3 B^T [pos][k]
__device__ __align__(16) float  d_Kv[NLn * Hn * Tc];
__device__ __align__(16) float2 d_lamT[NLn * Hn * Nn];              // lambda^128

// ---------------- helpers ----------------
__device__ __forceinline__ void cp16h(__half* dst, const __half* src) {
    uint32_t d = (uint32_t)__cvta_generic_to_shared(dst);
    asm volatile("cp.async.cg.shared.global [%0], [%1], 16;\n" :: "r"(d), "l"(src));
}
__device__ __forceinline__ void cp_commit() {
    asm volatile("cp.async.commit_group;\n");
}
template <int N>
__device__ __forceinline__ void cp_wait() {
    asm volatile("cp.async.wait_group %0;\n" :: "n"(N));
}

__device__ __forceinline__ void mma_f16(float* d, const uint32_t* a, const uint32_t* b) {
    asm volatile(
        "mma.sync.aligned.m16n8k16.row.col.f32.f16.f16.f32 "
        "{%0,%1,%2,%3}, {%4,%5,%6,%7}, {%8,%9}, {%0,%1,%2,%3};\n"
        : "+f"(d[0]), "+f"(d[1]), "+f"(d[2]), "+f"(d[3])
        : "r"(a[0]), "r"(a[1]), "r"(a[2]), "r"(a[3]), "r"(b[0]), "r"(b[1]));
}

__device__ __forceinline__ void ldsm_x4(uint32_t* r, uint32_t addr) {
    asm volatile("ldmatrix.sync.aligned.m8n8.x4.shared.b16 {%0,%1,%2,%3}, [%4];"
        : "=r"(r[0]), "=r"(r[1]), "=r"(r[2]), "=r"(r[3]) : "r"(addr));
}
__device__ __forceinline__ void ldsm_x4_t(uint32_t* r, uint32_t addr) {
    asm volatile("ldmatrix.sync.aligned.m8n8.x4.trans.shared.b16 {%0,%1,%2,%3}, [%4];"
        : "=r"(r[0]), "=r"(r[1]), "=r"(r[2]), "=r"(r[3]) : "r"(addr));
}

__device__ __forceinline__ float gelu_fast(float x) {
    float t2 = 1.5957691216057308f * fmaf(0.044715f, x * x * x, x);
    return x * (1.f / (1.f + __expf(-t2)));
}

// ---------------- param prep ----------------
__global__ __launch_bounds__(256) void prep_ssm(
    const float* __restrict__ log_dt, const float* __restrict__ logA_re,
    const float* __restrict__ A_im,   const float* __restrict__ Cp)
{
    int idx = blockIdx.x * 256 + threadIdx.x;      // NL*H*N = 32768
    int i = idx / (Hn * Nn);
    int h = (idx / Nn) % Hn;
    float dt  = expf(log_dt[i * Hn + h]);
    float aRe = -expf(logA_re[idx]);
    float aIm = A_im[idx];
    float er  = expf(aRe * dt);
    float ang = aIm * dt;
    float lr = er * cosf(ang), li = er * sinf(ang);
    float nr = lr - 1.f, ni = li;
    float inv = 1.f / (aRe * aRe + aIm * aIm);
    float qr = (nr * aRe + ni * aIm) * inv;
    float qi = (ni * aRe - nr * aIm) * inv;
    float cr = Cp[2 * idx], ci = Cp[2 * idx + 1];
    float Ctr = cr * qr - ci * qi;
    float Cti = cr * qi + ci * qr;
    d_SSMP[idx] = make_float4(lr, li, 2.f * Ctr, 2.f * Cti);
}

__global__ __launch_bounds__(256) void prep_pow()
{
    int gw = blockIdx.x * 8 + (threadIdx.x >> 5);   // 0..1023 = layer*256+h
    int n  = threadIdx.x & 31;
    float4 p = d_SSMP[gw * 32 + n];
    float lr = p.x, li = p.y, tcr = p.z, tci = p.w;
    float curr = 1.f, curi = 0.f;
    __half* W1p = d_W1h + (size_t)gw * (64 * 128);
    __half* B3p = d_B3h + (size_t)gw * (128 * 192);
    float* Kvp = d_Kv + gw * Tc;
    for (int j = 0; j <= 128; j++) {
        if (j < 128) {
            float kr = tcr * curr - tci * curi;
            float ki = tcr * curi + tci * curr;
            W1p[n * 128 + (127 - j)]        = __float2half_rn(kr);
            W1p[(32 + n) * 128 + (127 - j)] = __float2half_rn(ki);
            float s = kr;
#pragma unroll
            for (int o = 16; o; o >>= 1) s += __shfl_xor_sync(0xffffffffu, s, o);
            if (n == 0) Kvp[j] = s;
        }
        if (j >= 1) {
            int i = j - 1;
            B3p[i * 192 + 128 + n] = __float2half_rn(curr);
            B3p[i * 192 + 160 + n] = __float2half_rn(-curi);
        }
        if (j == 128) d_lamT[gw * 32 + n] = make_float2(curr, curi);
        float nr2 = curr * lr - curi * li;
        curi = curr * li + curi * lr;
        curr = nr2;
    }
}

__global__ __launch_bounds__(128) void prep_tk(const float* __restrict__ Dp)
{
    int gw = blockIdx.x;
    int i  = threadIdx.x;
    __shared__ float Ks[Tc];
    Ks[i] = d_Kv[gw * Tc + i];
    __syncthreads();
    float Dh = Dp[gw];
    __half* B3p = d_B3h + (size_t)gw * (128 * 192);
    for (int j = 0; j < 128; j++) {
        float v = 0.f;
        if (i >= j) v = Ks[i - j] + (i == j ? Dh : 0.f);
        B3p[i * 192 + j] = __float2half_rn(v);
    }
}

__global__ __launch_bounds__(256) void prep_w2t(
    const float* __restrict__ W_glu, const float* __restrict__ b_glu)
{
    int idx = blockIdx.x * 256 + threadIdx.x;      // NL*512*256 = 524288
    int l = idx >> 17;
    int rem = idx & 131071;
    int row = rem >> 8;
    int k = rem & 255;
    int tile = row >> 7;
    int rr = row & 127;
    int col = (rr < 64) ? (tile * 64 + rr) : (Hn + tile * 64 + (rr - 64));
    d_W2th[idx] = __float2half_rn(W_glu[((size_t)l * Hn + k) * (2 * Hn) + col]);
    if (idx < NLn * 512) {
        int l2 = idx >> 9, row2 = idx & 511;
        int t2 = row2 >> 7, r2 = row2 & 127;
        int c2 = (r2 < 64) ? (t2 * 64 + r2) : (Hn + t2 * 64 + (r2 - 64));
        d_b2t[idx] = b_glu[l2 * 512 + c2];
    }
}

// ---------------- input projection ----------------
__global__ __launch_bounds__(256) void in_proj(
    const float* __restrict__ x, const float* __restrict__ W, const float* __restrict__ bias)
{
    __shared__ float xs[32][DINn];
    int tid = threadIdx.x;
    int r0 = blockIdx.x * 32;
    for (int t = tid; t < 32 * DINn; t += 256)
        xs[t / DINn][t % DINn] = x[(size_t)r0 * DINn + t];
    float w[DINn];
#pragma unroll
    for (int k = 0; k < DINn; k++) w[k] = W[k * Hn + tid];
    float bv = bias[tid];
    __syncthreads();
#pragma unroll 4
    for (int r = 0; r < 32; r++) {
        float a = bv;
#pragma unroll
        for (int k = 0; k < DINn; k++) a = fmaf(xs[r][k], w[k], a);
        d_X[((size_t)(r0 + r)) * Hn + tid] = a;
    }
}

// ---- LayerNorm: Ztr (fp16 transposed, GEMM A) + Zl (fp32 straight, residual) ----
__global__ __launch_bounds__(256) void ln_t_kernel(
    int layer, const float* __restrict__ ln_g, const float* __restrict__ ln_b)
{
    __shared__ float tile[32][257];
    __shared__ float mu[32], sc[32];
    int b  = blockIdx.y;
    int l0 = blockIdx.x * 32;
    int tid = threadIdx.x, lane = tid & 31, wid = tid >> 5;
    const float* Xb = d_X + (size_t)b * Ln * Hn;
#pragma unroll
    for (int r = 0; r < 32; r++) {
        int l = l0 + r;
        tile[r][tid] = (l < Ln) ? Xb[(size_t)l * Hn + tid] : 0.f;
    }
    __syncthreads();
#pragma unroll
    for (int rr = 0; rr < 4; rr++) {
        int r = wid * 4 + rr;
        float s = 0.f, q = 0.f;
#pragma unroll
        for (int k = 0; k < 8; k++) {
            float v = tile[r][k * 32 + lane];
            s += v; q += v * v;
        }
#pragma unroll
        for (int o = 16; o; o >>= 1) {
            s += __shfl_xor_sync(0xffffffffu, s, o);
            q += __shfl_xor_sync(0xffffffffu, q, o);
        }
        if (lane == 0) {
            float m = s * (1.f / 256.f);
            float v = q * (1.f / 256.f) - m * m;
            mu[r] = m;
            sc[r] = rsqrtf(v + 1e-5f);
        }
    }
    __syncthreads();
    const float* g  = ln_g + layer * Hn;
    const float* bb = ln_b + layer * Hn;
    float gh = g[tid], bh = bb[tid];
    float* Zlb = d_Zl + (size_t)b * Ln * Hn;
#pragma unroll 4
    for (int r = 0; r < 32; r++) {
        int l = l0 + r;
        if (l < Ln)
            Zlb[(size_t)l * Hn + tid] = (tile[r][tid] - mu[r]) * sc[r] * gh + bh;
    }
    __half* Zrb = d_Ztr + (size_t)b * Hn * LP;
    int l = l0 + lane;
    if (l < Ln) {
        float m = mu[lane], s = sc[lane];
#pragma unroll
        for (int hi = 0; hi < 32; hi++) {
            int h = wid * 32 + hi;
            float zv = (tile[lane][h] - m) * s * g[h] + bb[h];
            Zrb[(size_t)h * LP + l] = __float2half_rn(zv);
        }
    }
}

// ---- stage 1: q = u_chunk @ W1 (M=640,N=64,K=128), single-shot resident smem -------
__global__ __launch_bounds__(256) void st1_kernel(int layer)
{
    extern __shared__ __half smh[];
    __half* As = smh;                      // [128][136]
    __half* Bs = smh + 128 * 136;          // [64][136]
    uint32_t sbase;
    asm("{ .reg .u64 t; cvta.to.shared.u64 t, %1; cvt.u32.u64 %0, t; }" : "=r"(sbase) : "l"(smh));
    int h  = blockIdx.y;
    int m0 = blockIdx.x * 128;
    int tid = threadIdx.x, lane = tid & 31, wid = tid >> 5;
    int wm = wid & 3, wn = wid >> 2;
    int tg = lane & 3, gp = lane >> 2;
    int grp = lane >> 3, lr = lane & 7;

    // fill A: 128 rows x 16 granules
    for (int i = 0; i < 8; i++) {
        int idx = tid + i * 256;
        int r = idx >> 4, g = idx & 15;
        int gm = m0 + r;
        int bbA = gm / Cc, ccA = gm % Cc;
        cp16h(As + r * 136 + g * 8,
              d_Ztr + ((size_t)(bbA * Hn + h)) * LP + ccA * Tc + g * 8);
    }
    // fill B: 64 rows x 16 granules
    const __half* W1p = d_W1h + (size_t)(layer * Hn + h) * (64 * 128);
    for (int i = 0; i < 4; i++) {
        int idx = tid + i * 256;
        int r = idx >> 4, g = idx & 15;
        cp16h(Bs + r * 136 + g * 8, W1p + r * 128 + g * 8);
    }
    cp_commit();
    cp_wait<0>();
    __syncthreads();

    float acc[2][4][4] = {};
    uint32_t aOff = (uint32_t)(((wm * 32 + (grp & 1) * 8 + lr) * 136 + (grp >> 1) * 8) * 2);
    uint32_t bOff = (uint32_t)((128 * 136 + (wn * 32 + (grp & 1) * 8 + lr) * 136 + (grp >> 1) * 8) * 2);
#pragma unroll
    for (int k2 = 0; k2 < 128; k2 += 16) {
        uint32_t af[2][4], bf[4][2];
#pragma unroll
        for (int mi = 0; mi < 2; mi++)
            ldsm_x4(af[mi], sbase + aOff + (uint32_t)((mi * 16 * 136 + k2) * 2));
#pragma unroll
        for (int nj = 0; nj < 2; nj++) {
            uint32_t q[4];
            ldsm_x4(q, sbase + bOff + (uint32_t)((nj * 16 * 136 + k2) * 2));
            bf[nj * 2][0] = q[0]; bf[nj * 2 + 1][0] = q[1];
            bf[nj * 2][1] = q[2]; bf[nj * 2 + 1][1] = q[3];
        }
#pragma unroll
        for (int mi = 0; mi < 2; mi++)
#pragma unroll
            for (int ni = 0; ni < 4; ni++)
                mma_f16(acc[mi][ni], af[mi], bf[ni]);
    }

#pragma unroll
    for (int mi = 0; mi < 2; mi++) {
#pragma unroll
        for (int ni = 0; ni < 4; ni++) {
            int n = wn * 32 + ni * 8 + tg * 2;
#pragma unroll
            for (int hf = 0; hf < 2; hf++) {
                int grow = m0 + wm * 32 + mi * 16 + gp + hf * 8;
                int b2 = grow / Cc, c2 = grow % Cc;
                size_t addr = ((size_t)(b2 * Hn + h) * Cc + c2) * 64 + n;
                d_Q[addr]     = acc[mi][ni][hf * 2];
                d_Q[addr + 1] = acc[mi][ni][hf * 2 + 1];
            }
        }
    }
}

// ---------------- stage 2: serial state pass -> Pt2h [h][m][64] fp16 ----------------
__global__ __launch_bounds__(256) void st2_kernel(int layer)
{
    int t = blockIdx.x * 256 + threadIdx.x;   // 131072
    int n = t & 31;
    int bh = t >> 5;
    int h = bh & 255, b = bh >> 8;
    float2 lt = d_lamT[(layer * Hn + h) * 32 + n];
    const float* qp = d_Q + (size_t)bh * (Cc * 64);
    __half* pp = d_Pt2h + ((size_t)h * Mrows + b * Cc) * 64;
    float pr = 0.f, pi = 0.f;
    for (int c = 0; c < Cc; c++) {
        pp[c * 64 + n]      = __float2half_rn(pr);
        pp[c * 64 + 32 + n] = __float2half_rn(pi);
        float qr = qp[c * 64 + n], qi = qp[c * 64 + 32 + n];
        float prn = fmaf(lt.x, pr, fmaf(-lt.y, pi, qr));
        pi        = fmaf(lt.y, pr, fmaf( lt.x, pi, qi));
        pr = prn;
    }
}

// ---- stage 3: y = [u|p] @ B3^T, gelu -> Gt fp16, single-shot resident smem ---------
__global__ __launch_bounds__(256) void st3_kernel(int layer)
{
    extern __shared__ __half smh[];
    __half* As = smh;                      // [128][200] (U 0..127 | P 128..191 | pad)
    __half* Bs = smh + 128 * 200;          // [128][200]
    uint32_t sbase;
    asm("{ .reg .u64 t; cvta.to.shared.u64 t, %1; cvt.u32.u64 %0, t; }" : "=r"(sbase) : "l"(smh));
    int h  = blockIdx.y;
    int m0 = blockIdx.x * 128;
    int tid = threadIdx.x, lane = tid & 31, wid = tid >> 5;
    int wm = wid & 3, wn = wid >> 2;
    int tg = lane & 3, gp = lane >> 2;
    int grp = lane >> 3, lr = lane & 7;

    // fill A: 128 rows x 24 granules (16 from Ztr, 8 from Pt2h)
    for (int i = 0; i < 12; i++) {
        int idx = tid + i * 256;
        int r = idx / 24, g = idx - r * 24;
        int gm = m0 + r;
        int bbA = gm / Cc, ccA = gm % Cc;
        const __half* src;
        if (g < 16)
            src = d_Ztr + ((size_t)(bbA * Hn + h)) * LP + ccA * Tc + g * 8;
        else
            src = d_Pt2h + ((size_t)h * Mrows + gm) * 64 + (g - 16) * 8;
        cp16h(As + r * 200 + g * 8, src);
    }
    // fill B: 128 rows x 24 granules
    const __half* B3p = d_B3h + (size_t)(layer * Hn + h) * (128 * 192);
    for (int i = 0; i < 12; i++) {
        int idx = tid + i * 256;
        int r = idx / 24, g = idx - r * 24;
        cp16h(Bs + r * 200 + g * 8, B3p + r * 192 + g * 8);
    }
    cp_commit();
    cp_wait<0>();
    __syncthreads();

    float acc[2][8][4] = {};
    uint32_t aOff = (uint32_t)(((wm * 32 + (grp & 1) * 8 + lr) * 200 + (grp >> 1) * 8) * 2);
    uint32_t bOff = (uint32_t)((128 * 200 + (wn * 64 + (grp & 1) * 8 + lr) * 200 + (grp >> 1) * 8) * 2);
#pragma unroll
    for (int k2 = 0; k2 < 192; k2 += 16) {
        uint32_t af[2][4], bf[8][2];
#pragma unroll
        for (int mi = 0; mi < 2; mi++)
            ldsm_x4(af[mi], sbase + aOff + (uint32_t)((mi * 16 * 200 + k2) * 2));
#pragma unroll
        for (int nj = 0; nj < 4; nj++) {
            uint32_t q[4];
            ldsm_x4(q, sbase + bOff + (uint32_t)((nj * 16 * 200 + k2) * 2));
            bf[nj * 2][0] = q[0]; bf[nj * 2 + 1][0] = q[1];
            bf[nj * 2][1] = q[2]; bf[nj * 2 + 1][1] = q[3];
        }
#pragma unroll
        for (int mi = 0; mi < 2; mi++)
#pragma unroll
            for (int ni = 0; ni < 8; ni++)
                mma_f16(acc[mi][ni], af[mi], bf[ni]);
    }

    __syncthreads();
    __half* stg = smh;                     // [128][136]
#pragma unroll
    for (int mi = 0; mi < 2; mi++) {
#pragma unroll
        for (int ni = 0; ni < 8; ni++) {
            int i = wn * 64 + ni * 8 + tg * 2;
#pragma unroll
            for (int hf = 0; hf < 2; hf++) {
                int ml = wm * 32 + mi * 16 + gp + hf * 8;
                __half2 v = __floats2half2_rn(gelu_fast(acc[mi][ni][hf * 2]),
                                              gelu_fast(acc[mi][ni][hf * 2 + 1]));
                *(__half2*)&stg[ml * 136 + i] = v;
            }
        }
    }
    __syncthreads();
#pragma unroll
    for (int it = 0; it < 8; it++) {
        int idx = tid + it * 256;
        int row = idx >> 4, g = idx & 15;
        int grow = m0 + row;
        int b2 = grow / Cc, c2 = grow % Cc;
        uint4 v = *(const uint4*)&stg[row * 136 + g * 8];
        *(uint4*)(d_Gt + ((size_t)(b2 * Hn + h)) * LP + c2 * Tc + g * 8) = v;
    }
}

// -------- GLU GEMM fp16 (ldmatrix, direct Gt): D[ch 128][l 128] = W2t x Gt^T --------
__global__ __launch_bounds__(256) void glu_kernel(int layer)
{
    extern __shared__ __half smh[];
    __shared__ float biasS[128];
    uint32_t sbase;
    asm("{ .reg .u64 t; cvta.to.shared.u64 t, %1; cvt.u32.u64 %0, t; }" : "=r"(sbase) : "l"(smh));
    const int tile = blockIdx.x;           // channel group 0..3
    const int l0   = blockIdx.y * 128;
    const int b    = blockIdx.z;
    const int m0   = tile * 128;
    int tid = threadIdx.x, lane = tid & 31, wid = tid >> 5;
    int wm = wid & 3, wn = wid >> 2;       // warp tile: 32 m x 64 n
    int tg = lane & 3, gp = lane >> 2;

    if (tid < 128) biasS[tid] = d_b2t[layer * 512 + m0 + tid];

    int rA = tid >> 1, gA = (tid & 1) * 2;
    const __half* Wp = d_W2th + (size_t)(layer * 512 + m0 + rA) * 256;
    int rB = tid >> 3, gB = tid & 7;       // B: 32 k-rows x 16 granules, 2 per thread
    const __half* Gp = d_Gt + ((size_t)(b * Hn + rB)) * LP + l0;

    float acc[2][8][4] = {};

    auto fill = [&](int s) {
        int kt = s * 32;
        __half* dA = smh + (s % 3) * (128 * 40);
        cp16h(dA + rA * 40 + gA * 8, Wp + kt + gA * 8);
        cp16h(dA + rA * 40 + (gA + 1) * 8, Wp + kt + (gA + 1) * 8);
        __half* dB = smh + 15360 + (s % 3) * (32 * 136);
        const __half* src = Gp + (size_t)kt * LP;
        cp16h(dB + rB * 136 + gB * 8, src + gB * 8);
        cp16h(dB + rB * 136 + (gB + 8) * 8, src + (gB + 8) * 8);
    };

    int grp = lane >> 3, lr = lane & 7;
    uint32_t aOff = (uint32_t)(((wm * 32 + (grp & 1) * 8 + lr) * 40 + (grp >> 1) * 8) * 2);
    uint32_t bOff = (uint32_t)((((grp & 1) * 8 + lr) * 136 + wn * 64 + (grp >> 1) * 8) * 2);

    fill(0); cp_commit();
    fill(1); cp_commit();
#pragma unroll
    for (int s = 0; s < 8; s++) {
        if (s < 7) cp_wait<1>(); else cp_wait<0>();
        __syncthreads();
        if (s + 2 < 8) { fill(s + 2); cp_commit(); }
        uint32_t aBuf = sbase + (uint32_t)((s % 3) * (128 * 40) * 2);
        uint32_t bBuf = sbase + (uint32_t)((15360 + (s % 3) * (32 * 136)) * 2);
#pragma unroll
        for (int k2 = 0; k2 < 32; k2 += 16) {
            uint32_t af[2][4], bf[8][2];
#pragma unroll
            for (int mi = 0; mi < 2; mi++)
                ldsm_x4(af[mi], aBuf + aOff + (uint32_t)((mi * 16 * 40 + k2) * 2));
#pragma unroll
            for (int nj = 0; nj < 4; nj++) {
                uint32_t q[4];
                ldsm_x4_t(q, bBuf + bOff + (uint32_t)((k2 * 136 + nj * 16) * 2));
                bf[nj * 2][0] = q[0]; bf[nj * 2][1] = q[1];
                bf[nj * 2 + 1][0] = q[2]; bf[nj * 2 + 1][1] = q[3];
            }
#pragma unroll
            for (int mi = 0; mi < 2; mi++)
#pragma unroll
                for (int ni = 0; ni < 8; ni++)
                    mma_f16(acc[mi][ni], af[mi], bf[ni]);
        }
    }

    // stage C[ch][l] (+bias) in fp32, then GLU + Zl residual, coalesced X writes
    __syncthreads();
    float* stgF = (float*)smh;             // [128 ch][133 l]
#pragma unroll
    for (int mi = 0; mi < 2; mi++) {
#pragma unroll
        for (int hf = 0; hf < 2; hf++) {
            int row = wm * 32 + mi * 16 + gp + hf * 8;
            float bv = biasS[row];
#pragma unroll
            for (int ni = 0; ni < 8; ni++) {
                int col = wn * 64 + ni * 8 + tg * 2;
                stgF[row * 133 + col]     = acc[mi][ni][hf * 2]     + bv;
                stgF[row * 133 + col + 1] = acc[mi][ni][hf * 2 + 1] + bv;
            }
        }
    }
    __syncthreads();
#pragma unroll
    for (int it = 0; it < 8; it++) {
        int idx = tid + it * 256;          // 2048 tasks = 128 l-rows x 16 float4
        int row_l = idx >> 4;
        int j = (idx & 15) * 4;            // channel within 64
        int gl = l0 + row_l;
        if (gl < Ln) {
            const float* Zp = d_Zl + ((size_t)b * Ln + gl) * Hn + tile * 64;
            float* Xp = d_X + ((size_t)b * Ln + gl) * Hn + tile * 64;
            float a0 = stgF[(j    ) * 133 + row_l], g0 = stgF[(64 + j    ) * 133 + row_l];
            float a1 = stgF[(j + 1) * 133 + row_l], g1 = stgF[(65 + j    ) * 133 + row_l];
            float a2 = stgF[(j + 2) * 133 + row_l], g2 = stgF[(66 + j    ) * 133 + row_l];
            float a3 = stgF[(j + 3) * 133 + row_l], g3 = stgF[(67 + j    ) * 133 + row_l];
            float4 o, z;
            o.x = a0 * (1.f / (1.f + __expf(-g0)));
            o.y = a1 * (1.f / (1.f + __expf(-g1)));
            o.z = a2 * (1.f / (1.f + __expf(-g2)));
            o.w = a3 * (1.f / (1.f + __expf(-g3)));
            z = *(const float4*)(Zp + j);
            o.x += z.x; o.y += z.y; o.z += z.z; o.w += z.w;
            *(float4*)(Xp + j) = o;
        }
    }
}

// ---------------- final LayerNorm -> d_out ----------------
__global__ __launch_bounds__(256) void final_ln(
    const float* __restrict__ g, const float* __restrict__ bb, float* __restrict__ out)
{
    int lane = threadIdx.x & 31, wid = threadIdx.x >> 5;
    size_t row = (size_t)blockIdx.x * 8 + wid;
    const float* xr = d_X + row * Hn;
    float v[8], s = 0.f, q = 0.f;
#pragma unroll
    for (int k = 0; k < 8; k++) {
        v[k] = xr[k * 32 + lane];
        s += v[k]; q += v[k] * v[k];
    }
#pragma unroll
    for (int o = 16; o; o >>= 1) {
        s += __shfl_xor_sync(0xffffffffu, s, o);
        q += __shfl_xor_sync(0xffffffffu, q, o);
    }
    float m  = s * (1.f / 256.f);
    float sc = rsqrtf(q * (1.f / 256.f) - m * m + 1e-5f);
#pragma unroll
    for (int k = 0; k < 8; k++) {
        int h = k * 32 + lane;
        out[row * Hn + h] = (v[k] - m) * sc * g[h] + bb[h];
    }
}

// ---------------- launch ----------------
extern "C" void kernel_launch(void* const* d_in, const int* in_sizes, int n_in,
                              void* d_out, int out_size)
{
    const float* x       = (const float*)d_in[0];
    const float* W_in    = (const float*)d_in[1];
    const float* b_in    = (const float*)d_in[2];
    const float* ln_g    = (const float*)d_in[3];
    const float* ln_b    = (const float*)d_in[4];
    const float* log_dt  = (const float*)d_in[5];
    const float* logA_re = (const float*)d_in[6];
    const float* A_im    = (const float*)d_in[7];
    const float* Cp      = (const float*)d_in[8];
    const float* Dp      = (const float*)d_in[9];
    const float* W_glu   = (const float*)d_in[10];
    const float* b_glu   = (const float*)d_in[11];
    const float* fn_g    = (const float*)d_in[12];
    const float* fn_b    = (const float*)d_in[13];
    float* out = (float*)d_out;

    const int smem_st1 = (128 * 136 + 64 * 136) * 2;          // 52224
    const int smem_st3 = (128 * 200 * 2) * 2;                 // 102400
    const int smem_glu = 128 * 133 * 4;                       // 68096 (>= mainloop 56832)
    cudaFuncSetAttribute(st1_kernel, cudaFuncAttributeMaxDynamicSharedMemorySize, smem_st1);
    cudaFuncSetAttribute(st3_kernel, cudaFuncAttributeMaxDynamicSharedMemorySize, smem_st3);
    cudaFuncSetAttribute(glu_kernel, cudaFuncAttributeMaxDynamicSharedMemorySize, smem_glu);

    prep_ssm<<<128, 256>>>(log_dt, logA_re, A_im, Cp);
    prep_pow<<<128, 256>>>();
    prep_tk<<<NLn * Hn, 128>>>(Dp);
    prep_w2t<<<2048, 256>>>(W_glu, b_glu);
    in_proj<<<2500, 256>>>(x, W_in, b_in);

    for (int i = 0; i < NLn; i++) {
        dim3 gln((Ln + 31) / 32, Bn);
        ln_t_kernel<<<gln, 256>>>(i, ln_g, ln_b);
        st1_kernel<<<dim3(Mrows / 128, Hn), 256, smem_st1>>>(i);
        st2_kernel<<<512, 256>>>(i);
        st3_kernel<<<dim3(Mrows / 128, Hn), 256, smem_st3>>>(i);
        glu_kernel<<<dim3(4, LP / 128, Bn), 256, smem_glu>>>(i);
    }
    final_ln<<<(Bn * Ln) / 8, 256>>>(fn_g, fn_b, out);
}

// round 15
// speedup vs baseline: 1.2283x; 1.1766x over previous
#include <cuda_runtime.h>
#include <cuda_fp16.h>
#include <cstdint>
#include <math.h>

#define Bn   16
#define Ln   5000
#define Hn   256
#define Nn   32
#define NLn  4
#define DINn 12
#define Tc   128          // chunk length
#define Cc   40           // chunks (padded length 5120)
#define LP   5120         // padded L
#define Mrows (Bn * Cc)   // 640 chunk-rows

// ---------------- scratch (device globals; zero-initialized) ----------------
__device__ __align__(16) float  d_X  [(size_t)Bn * Ln * Hn];   // activations (B, L, H)
__device__ __align__(16) float  d_Zl [(size_t)Bn * Ln * Hn];   // LN output fp32 (B, L, H) residual
__device__ __align__(16) __half d_Ztr[(size_t)Bn * Hn * LP];   // LN output fp16 (B,H,Lpad), pad=0
__device__ __align__(16) __half d_Gt [(size_t)Bn * Hn * LP];   // fp16 gelu(y), (B, H, Lpad)
__device__ __align__(16) float4 d_SSMP[NLn * Hn * Nn];         // (lam_re, lam_im, 2Ct_re, 2Ct_im)
__device__ __align__(16) __half d_W2th[(size_t)NLn * 512 * Hn];// W_glu^T grouped rows, k-contig
__device__ __align__(16) float  d_b2t[NLn * 2 * Hn];
__device__ __align__(16) float  d_Q   [(size_t)Bn * Hn * Cc * 64];  // chunk state contributions
__device__ __align__(16) __half d_Pt2h[(size_t)Hn * Mrows * 64];    // fp16 chunk-start states
__device__ __align__(16) __half d_W1h[(size_t)NLn * Hn * 64 * 128]; // stage-1 B^T [n][k]
__device__ __align__(16) __half d_B3h[(size_t)NLn * Hn * 128 * 192];// stage-3 B^T [pos][k]
__device__ __align__(16) float  d_Kv[NLn * Hn * Tc];
__device__ __align__(16) float2 d_lamT[NLn * Hn * Nn];              // lambda^128

// ---------------- helpers ----------------
__device__ __forceinline__ void cp16h(__half* dst, const __half* src) {
    uint32_t d = (uint32_t)__cvta_generic_to_shared(dst);
    asm volatile("cp.async.cg.shared.global [%0], [%1], 16;\n" :: "r"(d), "l"(src));
}
__device__ __forceinline__ void cp_commit() {
    asm volatile("cp.async.commit_group;\n");
}
template <int N>
__device__ __forceinline__ void cp_wait() {
    asm volatile("cp.async.wait_group %0;\n" :: "n"(N));
}

__device__ __forceinline__ void mma_f16(float* d, const uint32_t* a, const uint32_t* b) {
    asm volatile(
        "mma.sync.aligned.m16n8k16.row.col.f32.f16.f16.f32 "
        "{%0,%1,%2,%3}, {%4,%5,%6,%7}, {%8,%9}, {%0,%1,%2,%3};\n"
        : "+f"(d[0]), "+f"(d[1]), "+f"(d[2]), "+f"(d[3])
        : "r"(a[0]), "r"(a[1]), "r"(a[2]), "r"(a[3]), "r"(b[0]), "r"(b[1]));
}

__device__ __forceinline__ void ldsm_x4(uint32_t* r, uint32_t addr) {
    asm volatile("ldmatrix.sync.aligned.m8n8.x4.shared.b16 {%0,%1,%2,%3}, [%4];"
        : "=r"(r[0]), "=r"(r[1]), "=r"(r[2]), "=r"(r[3]) : "r"(addr));
}
__device__ __forceinline__ void ldsm_x4_t(uint32_t* r, uint32_t addr) {
    asm volatile("ldmatrix.sync.aligned.m8n8.x4.trans.shared.b16 {%0,%1,%2,%3}, [%4];"
        : "=r"(r[0]), "=r"(r[1]), "=r"(r[2]), "=r"(r[3]) : "r"(addr));
}

__device__ __forceinline__ float gelu_fast(float x) {
    float t2 = 1.5957691216057308f * fmaf(0.044715f, x * x * x, x);
    return x * (1.f / (1.f + __expf(-t2)));
}

// ---------------- param prep ----------------
__global__ __launch_bounds__(256) void prep_ssm(
    const float* __restrict__ log_dt, const float* __restrict__ logA_re,
    const float* __restrict__ A_im,   const float* __restrict__ Cp)
{
    int idx = blockIdx.x * 256 + threadIdx.x;      // NL*H*N = 32768
    int i = idx / (Hn * Nn);
    int h = (idx / Nn) % Hn;
    float dt  = expf(log_dt[i * Hn + h]);
    float aRe = -expf(logA_re[idx]);
    float aIm = A_im[idx];
    float er  = expf(aRe * dt);
    float ang = aIm * dt;
    float lr = er * cosf(ang), li = er * sinf(ang);
    float nr = lr - 1.f, ni = li;
    float inv = 1.f / (aRe * aRe + aIm * aIm);
    float qr = (nr * aRe + ni * aIm) * inv;
    float qi = (ni * aRe - nr * aIm) * inv;
    float cr = Cp[2 * idx], ci = Cp[2 * idx + 1];
    float Ctr = cr * qr - ci * qi;
    float Cti = cr * qi + ci * qr;
    d_SSMP[idx] = make_float4(lr, li, 2.f * Ctr, 2.f * Cti);
}

// powers of lambda; W1 staged in smem then written coalesced
__global__ __launch_bounds__(256) void prep_pow()
{
    extern __shared__ __half ws[];                  // 8 warps x [64][136]
    int tid = threadIdx.x, wid = tid >> 5, n = tid & 31;
    int gw = blockIdx.x * 8 + wid;                  // 0..1023 = layer*256+h
    __half* W1s = ws + wid * (64 * 136);
    float4 p = d_SSMP[gw * 32 + n];
    float lr = p.x, li = p.y, tcr = p.z, tci = p.w;
    float curr = 1.f, curi = 0.f;
    __half* B3p = d_B3h + (size_t)gw * (128 * 192);
    float* Kvp = d_Kv + gw * Tc;
    for (int j = 0; j <= 128; j++) {
        if (j < 128) {
            float kr = tcr * curr - tci * curi;
            float ki = tcr * curi + tci * curr;
            W1s[n * 136 + (127 - j)]        = __float2half_rn(kr);
            W1s[(32 + n) * 136 + (127 - j)] = __float2half_rn(ki);
            float s = kr;
#pragma unroll
            for (int o = 16; o; o >>= 1) s += __shfl_xor_sync(0xffffffffu, s, o);
            if (n == 0) Kvp[j] = s;
        }
        if (j >= 1) {
            int i = j - 1;
            B3p[i * 192 + 128 + n] = __float2half_rn(curr);   // lane-contiguous, coalesced
            B3p[i * 192 + 160 + n] = __float2half_rn(-curi);
        }
        if (j == 128) d_lamT[gw * 32 + n] = make_float2(curr, curi);
        float nr2 = curr * lr - curi * li;
        curi = curr * li + curi * lr;
        curr = nr2;
    }
    __syncwarp();
    // coalesced writeout of the 64x128 W1 tile
    __half* W1p = d_W1h + (size_t)gw * (64 * 128);
#pragma unroll
    for (int it = 0; it < 32; it++) {
        int idx = it * 32 + n;                      // 1024 uint4 granules
        int r = idx >> 4, g = idx & 15;
        *(uint4*)(W1p + r * 128 + g * 8) = *(const uint4*)&W1s[r * 136 + g * 8];
    }
}

// Toeplitz rows of B3 (D on diagonal); thread = j (contiguous) -> coalesced stores
__global__ __launch_bounds__(128) void prep_tk(const float* __restrict__ Dp)
{
    int gw = blockIdx.x;
    int j  = threadIdx.x;         // 0..127, contiguous within each row
    __shared__ float Ks[Tc];
    Ks[j] = d_Kv[gw * Tc + j];
    __syncthreads();
    float Dh = Dp[gw];
    __half* B3p = d_B3h + (size_t)gw * (128 * 192);
    for (int i = 0; i < 128; i++) {
        float v = 0.f;
        if (i >= j) v = Ks[i - j] + (i == j ? Dh : 0.f);
        B3p[i * 192 + j] = __float2half_rn(v);
    }
}

__global__ __launch_bounds__(256) void prep_w2t(
    const float* __restrict__ W_glu, const float* __restrict__ b_glu)
{
    int idx = blockIdx.x * 256 + threadIdx.x;      // NL*512*256 = 524288
    int l = idx >> 17;
    int rem = idx & 131071;
    int row = rem >> 8;
    int k = rem & 255;
    int tile = row >> 7;
    int rr = row & 127;
    int col = (rr < 64) ? (tile * 64 + rr) : (Hn + tile * 64 + (rr - 64));
    d_W2th[idx] = __float2half_rn(W_glu[((size_t)l * Hn + k) * (2 * Hn) + col]);
    if (idx < NLn * 512) {
        int l2 = idx >> 9, row2 = idx & 511;
        int t2 = row2 >> 7, r2 = row2 & 127;
        int c2 = (r2 < 64) ? (t2 * 64 + r2) : (Hn + t2 * 64 + (r2 - 64));
        d_b2t[idx] = b_glu[l2 * 512 + c2];
    }
}

// ---------------- input projection ----------------
__global__ __launch_bounds__(256) void in_proj(
    const float* __restrict__ x, const float* __restrict__ W, const float* __restrict__ bias)
{
    __shared__ float xs[32][DINn];
    int tid = threadIdx.x;
    int r0 = blockIdx.x * 32;
    for (int t = tid; t < 32 * DINn; t += 256)
        xs[t / DINn][t % DINn] = x[(size_t)r0 * DINn + t];
    float w[DINn];
#pragma unroll
    for (int k = 0; k < DINn; k++) w[k] = W[k * Hn + tid];
    float bv = bias[tid];
    __syncthreads();
#pragma unroll 4
    for (int r = 0; r < 32; r++) {
        float a = bv;
#pragma unroll
        for (int k = 0; k < DINn; k++) a = fmaf(xs[r][k], w[k], a);
        d_X[((size_t)(r0 + r)) * Hn + tid] = a;
    }
}

// ---- LayerNorm: Ztr (fp16 transposed, GEMM A) + Zl (fp32 straight, residual) ----
__global__ __launch_bounds__(256) void ln_t_kernel(
    int layer, const float* __restrict__ ln_g, const float* __restrict__ ln_b)
{
    __shared__ float tile[32][257];
    __shared__ float mu[32], sc[32];
    int b  = blockIdx.y;
    int l0 = blockIdx.x * 32;
    int tid = threadIdx.x, lane = tid & 31, wid = tid >> 5;
    const float* Xb = d_X + (size_t)b * Ln * Hn;
#pragma unroll
    for (int r = 0; r < 32; r++) {
        int l = l0 + r;
        tile[r][tid] = (l < Ln) ? Xb[(size_t)l * Hn + tid] : 0.f;
    }
    __syncthreads();
#pragma unroll
    for (int rr = 0; rr < 4; rr++) {
        int r = wid * 4 + rr;
        float s = 0.f, q = 0.f;
#pragma unroll
        for (int k = 0; k < 8; k++) {
            float v = tile[r][k * 32 + lane];
            s += v; q += v * v;
        }
#pragma unroll
        for (int o = 16; o; o >>= 1) {
            s += __shfl_xor_sync(0xffffffffu, s, o);
            q += __shfl_xor_sync(0xffffffffu, q, o);
        }
        if (lane == 0) {
            float m = s * (1.f / 256.f);
            float v = q * (1.f / 256.f) - m * m;
            mu[r] = m;
            sc[r] = rsqrtf(v + 1e-5f);
        }
    }
    __syncthreads();
    const float* g  = ln_g + layer * Hn;
    const float* bb = ln_b + layer * Hn;
    float gh = g[tid], bh = bb[tid];
    float* Zlb = d_Zl + (size_t)b * Ln * Hn;
#pragma unroll 4
    for (int r = 0; r < 32; r++) {
        int l = l0 + r;
        if (l < Ln)
            Zlb[(size_t)l * Hn + tid] = (tile[r][tid] - mu[r]) * sc[r] * gh + bh;
    }
    __half* Zrb = d_Ztr + (size_t)b * Hn * LP;
    int l = l0 + lane;
    if (l < Ln) {
        float m = mu[lane], s = sc[lane];
#pragma unroll
        for (int hi = 0; hi < 32; hi++) {
            int h = wid * 32 + hi;
            float zv = (tile[lane][h] - m) * s * g[h] + bb[h];
            Zrb[(size_t)h * LP + l] = __float2half_rn(zv);
        }
    }
}

// ---- stage 1: q = u_chunk @ W1 (M=640,N=64,K=128), single-shot resident smem -------
__global__ __launch_bounds__(256) void st1_kernel(int layer)
{
    extern __shared__ __half smh[];
    __half* As = smh;                      // [128][136]
    __half* Bs = smh + 128 * 136;          // [64][136]
    uint32_t sbase;
    asm("{ .reg .u64 t; cvta.to.shared.u64 t, %1; cvt.u32.u64 %0, t; }" : "=r"(sbase) : "l"(smh));
    int h  = blockIdx.y;
    int m0 = blockIdx.x * 128;
    int tid = threadIdx.x, lane = tid & 31, wid = tid >> 5;
    int wm = wid & 3, wn = wid >> 2;
    int tg = lane & 3, gp = lane >> 2;
    int grp = lane >> 3, lr = lane & 7;

    for (int i = 0; i < 8; i++) {
        int idx = tid + i * 256;
        int r = idx >> 4, g = idx & 15;
        int gm = m0 + r;
        int bbA = gm / Cc, ccA = gm % Cc;
        cp16h(As + r * 136 + g * 8,
              d_Ztr + ((size_t)(bbA * Hn + h)) * LP + ccA * Tc + g * 8);
    }
    const __half* W1p = d_W1h + (size_t)(layer * Hn + h) * (64 * 128);
    for (int i = 0; i < 4; i++) {
        int idx = tid + i * 256;
        int r = idx >> 4, g = idx & 15;
        cp16h(Bs + r * 136 + g * 8, W1p + r * 128 + g * 8);
    }
    cp_commit();
    cp_wait<0>();
    __syncthreads();

    float acc[2][4][4] = {};
    uint32_t aOff = (uint32_t)(((wm * 32 + (grp & 1) * 8 + lr) * 136 + (grp >> 1) * 8) * 2);
    uint32_t bOff = (uint32_t)((128 * 136 + (wn * 32 + (grp & 1) * 8 + lr) * 136 + (grp >> 1) * 8) * 2);
#pragma unroll
    for (int k2 = 0; k2 < 128; k2 += 16) {
        uint32_t af[2][4], bf[4][2];
#pragma unroll
        for (int mi = 0; mi < 2; mi++)
            ldsm_x4(af[mi], sbase + aOff + (uint32_t)((mi * 16 * 136 + k2) * 2));
#pragma unroll
        for (int nj = 0; nj < 2; nj++) {
            uint32_t q[4];
            ldsm_x4(q, sbase + bOff + (uint32_t)((nj * 16 * 136 + k2) * 2));
            bf[nj * 2][0] = q[0]; bf[nj * 2 + 1][0] = q[1];
            bf[nj * 2][1] = q[2]; bf[nj * 2 + 1][1] = q[3];
        }
#pragma unroll
        for (int mi = 0; mi < 2; mi++)
#pragma unroll
            for (int ni = 0; ni < 4; ni++)
                mma_f16(acc[mi][ni], af[mi], bf[ni]);
    }

#pragma unroll
    for (int mi = 0; mi < 2; mi++) {
#pragma unroll
        for (int ni = 0; ni < 4; ni++) {
            int n = wn * 32 + ni * 8 + tg * 2;
#pragma unroll
            for (int hf = 0; hf < 2; hf++) {
                int grow = m0 + wm * 32 + mi * 16 + gp + hf * 8;
                int b2 = grow / Cc, c2 = grow % Cc;
                size_t addr = ((size_t)(b2 * Hn + h) * Cc + c2) * 64 + n;
                d_Q[addr]     = acc[mi][ni][hf * 2];
                d_Q[addr + 1] = acc[mi][ni][hf * 2 + 1];
            }
        }
    }
}

// ---------------- stage 2: serial state pass -> Pt2h [h][m][64] fp16 ----------------
__global__ __launch_bounds__(256) void st2_kernel(int layer)
{
    int t = blockIdx.x * 256 + threadIdx.x;   // 131072
    int n = t & 31;
    int bh = t >> 5;
    int h = bh & 255, b = bh >> 8;
    float2 lt = d_lamT[(layer * Hn + h) * 32 + n];
    const float* qp = d_Q + (size_t)bh * (Cc * 64);
    __half* pp = d_Pt2h + ((size_t)h * Mrows + b * Cc) * 64;
    float pr = 0.f, pi = 0.f;
    for (int c = 0; c < Cc; c++) {
        pp[c * 64 + n]      = __float2half_rn(pr);
        pp[c * 64 + 32 + n] = __float2half_rn(pi);
        float qr = qp[c * 64 + n], qi = qp[c * 64 + 32 + n];
        float prn = fmaf(lt.x, pr, fmaf(-lt.y, pi, qr));
        pi        = fmaf(lt.y, pr, fmaf( lt.x, pi, qi));
        pr = prn;
    }
}

// ---- stage 3: y = [u|p] @ B3^T, gelu -> Gt fp16, single-shot resident smem ---------
__global__ __launch_bounds__(256) void st3_kernel(int layer)
{
    extern __shared__ __half smh[];
    __half* As = smh;                      // [128][200] (U 0..127 | P 128..191 | pad)
    __half* Bs = smh + 128 * 200;          // [128][200]
    uint32_t sbase;
    asm("{ .reg .u64 t; cvta.to.shared.u64 t, %1; cvt.u32.u64 %0, t; }" : "=r"(sbase) : "l"(smh));
    int h  = blockIdx.y;
    int m0 = blockIdx.x * 128;
    int tid = threadIdx.x, lane = tid & 31, wid = tid >> 5;
    int wm = wid & 3, wn = wid >> 2;
    int tg = lane & 3, gp = lane >> 2;
    int grp = lane >> 3, lr = lane & 7;

    for (int i = 0; i < 12; i++) {
        int idx = tid + i * 256;
        int r = idx / 24, g = idx - r * 24;
        int gm = m0 + r;
        int bbA = gm / Cc, ccA = gm % Cc;
        const __half* src;
        if (g < 16)
            src = d_Ztr + ((size_t)(bbA * Hn + h)) * LP + ccA * Tc + g * 8;
        else
            src = d_Pt2h + ((size_t)h * Mrows + gm) * 64 + (g - 16) * 8;
        cp16h(As + r * 200 + g * 8, src);
    }
    const __half* B3p = d_B3h + (size_t)(layer * Hn + h) * (128 * 192);
    for (int i = 0; i < 12; i++) {
        int idx = tid + i * 256;
        int r = idx / 24, g = idx - r * 24;
        cp16h(Bs + r * 200 + g * 8, B3p + r * 192 + g * 8);
    }
    cp_commit();
    cp_wait<0>();
    __syncthreads();

    float acc[2][8][4] = {};
    uint32_t aOff = (uint32_t)(((wm * 32 + (grp & 1) * 8 + lr) * 200 + (grp >> 1) * 8) * 2);
    uint32_t bOff = (uint32_t)((128 * 200 + (wn * 64 + (grp & 1) * 8 + lr) * 200 + (grp >> 1) * 8) * 2);
#pragma unroll
    for (int k2 = 0; k2 < 192; k2 += 16) {
        uint32_t af[2][4], bf[8][2];
#pragma unroll
        for (int mi = 0; mi < 2; mi++)
            ldsm_x4(af[mi], sbase + aOff + (uint32_t)((mi * 16 * 200 + k2) * 2));
#pragma unroll
        for (int nj = 0; nj < 4; nj++) {
            uint32_t q[4];
            ldsm_x4(q, sbase + bOff + (uint32_t)((nj * 16 * 200 + k2) * 2));
            bf[nj * 2][0] = q[0]; bf[nj * 2 + 1][0] = q[1];
            bf[nj * 2][1] = q[2]; bf[nj * 2 + 1][1] = q[3];
        }
#pragma unroll
        for (int mi = 0; mi < 2; mi++)
#pragma unroll
            for (int ni = 0; ni < 8; ni++)
                mma_f16(acc[mi][ni], af[mi], bf[ni]);
    }

    __syncthreads();
    __half* stg = smh;                     // [128][136]
#pragma unroll
    for (int mi = 0; mi < 2; mi++) {
#pragma unroll
        for (int ni = 0; ni < 8; ni++) {
            int i = wn * 64 + ni * 8 + tg * 2;
#pragma unroll
            for (int hf = 0; hf < 2; hf++) {
                int ml = wm * 32 + mi * 16 + gp + hf * 8;
                __half2 v = __floats2half2_rn(gelu_fast(acc[mi][ni][hf * 2]),
                                              gelu_fast(acc[mi][ni][hf * 2 + 1]));
                *(__half2*)&stg[ml * 136 + i] = v;
            }
        }
    }
    __syncthreads();
#pragma unroll
    for (int it = 0; it < 8; it++) {
        int idx = tid + it * 256;
        int row = idx >> 4, g = idx & 15;
        int grow = m0 + row;
        int b2 = grow / Cc, c2 = grow % Cc;
        uint4 v = *(const uint4*)&stg[row * 136 + g * 8];
        *(uint4*)(d_Gt + ((size_t)(b2 * Hn + h)) * LP + c2 * Tc + g * 8) = v;
    }
}

// -------- GLU GEMM fp16 (ldmatrix, direct Gt): D[ch 128][l 128] = W2t x Gt^T --------
__global__ __launch_bounds__(256) void glu_kernel(int layer)
{
    extern __shared__ __half smh[];
    __shared__ float biasS[128];
    uint32_t sbase;
    asm("{ .reg .u64 t; cvta.to.shared.u64 t, %1; cvt.u32.u64 %0, t; }" : "=r"(sbase) : "l"(smh));
    const int tile = blockIdx.x;           // channel group 0..3
    const int l0   = blockIdx.y * 128;
    const int b    = blockIdx.z;
    const int m0   = tile * 128;
    int tid = threadIdx.x, lane = tid & 31, wid = tid >> 5;
    int wm = wid & 3, wn = wid >> 2;       // warp tile: 32 m x 64 n
    int tg = lane & 3, gp = lane >> 2;

    if (tid < 128) biasS[tid] = d_b2t[layer * 512 + m0 + tid];

    int rA = tid >> 1, gA = (tid & 1) * 2;
    const __half* Wp = d_W2th + (size_t)(layer * 512 + m0 + rA) * 256;
    int rB = tid >> 3, gB = tid & 7;       // B: 32 k-rows x 16 granules, 2 per thread
    const __half* Gp = d_Gt + ((size_t)(b * Hn + rB)) * LP + l0;

    float acc[2][8][4] = {};

    auto fill = [&](int s) {
        int kt = s * 32;
        __half* dA = smh + (s % 3) * (128 * 40);
        cp16h(dA + rA * 40 + gA * 8, Wp + kt + gA * 8);
        cp16h(dA + rA * 40 + (gA + 1) * 8, Wp + kt + (gA + 1) * 8);
        __half* dB = smh + 15360 + (s % 3) * (32 * 136);
        const __half* src = Gp + (size_t)kt * LP;
        cp16h(dB + rB * 136 + gB * 8, src + gB * 8);
        cp16h(dB + rB * 136 + (gB + 8) * 8, src + (gB + 8) * 8);
    };

    int grp = lane >> 3, lr = lane & 7;
    uint32_t aOff = (uint32_t)(((wm * 32 + (grp & 1) * 8 + lr) * 40 + (grp >> 1) * 8) * 2);
    uint32_t bOff = (uint32_t)((((grp & 1) * 8 + lr) * 136 + wn * 64 + (grp >> 1) * 8) * 2);

    fill(0); cp_commit();
    fill(1); cp_commit();
#pragma unroll
    for (int s = 0; s < 8; s++) {
        if (s < 7) cp_wait<1>(); else cp_wait<0>();
        __syncthreads();
        if (s + 2 < 8) { fill(s + 2); cp_commit(); }
        uint32_t aBuf = sbase + (uint32_t)((s % 3) * (128 * 40) * 2);
        uint32_t bBuf = sbase + (uint32_t)((15360 + (s % 3) * (32 * 136)) * 2);
#pragma unroll
        for (int k2 = 0; k2 < 32; k2 += 16) {
            uint32_t af[2][4], bf[8][2];
#pragma unroll
            for (int mi = 0; mi < 2; mi++)
                ldsm_x4(af[mi], aBuf + aOff + (uint32_t)((mi * 16 * 40 + k2) * 2));
#pragma unroll
            for (int nj = 0; nj < 4; nj++) {
                uint32_t q[4];
                ldsm_x4_t(q, bBuf + bOff + (uint32_t)((k2 * 136 + nj * 16) * 2));
                bf[nj * 2][0] = q[0]; bf[nj * 2][1] = q[1];
                bf[nj * 2 + 1][0] = q[2]; bf[nj * 2 + 1][1] = q[3];
            }
#pragma unroll
            for (int mi = 0; mi < 2; mi++)
#pragma unroll
                for (int ni = 0; ni < 8; ni++)
                    mma_f16(acc[mi][ni], af[mi], bf[ni]);
        }
    }

    // stage C[ch][l] (+bias) in fp32, then GLU + Zl residual, coalesced X writes
    __syncthreads();
    float* stgF = (float*)smh;             // [128 ch][133 l]
#pragma unroll
    for (int mi = 0; mi < 2; mi++) {
#pragma unroll
        for (int hf = 0; hf < 2; hf++) {
            int row = wm * 32 + mi * 16 + gp + hf * 8;
            float bv = biasS[row];
#pragma unroll
            for (int ni = 0; ni < 8; ni++) {
                int col = wn * 64 + ni * 8 + tg * 2;
                stgF[row * 133 + col]     = acc[mi][ni][hf * 2]     + bv;
                stgF[row * 133 + col + 1] = acc[mi][ni][hf * 2 + 1] + bv;
            }
        }
    }
    __syncthreads();
#pragma unroll
    for (int it = 0; it < 8; it++) {
        int idx = tid + it * 256;          // 2048 tasks = 128 l-rows x 16 float4
        int row_l = idx >> 4;
        int j = (idx & 15) * 4;            // channel within 64
        int gl = l0 + row_l;
        if (gl < Ln) {
            const float* Zp = d_Zl + ((size_t)b * Ln + gl) * Hn + tile * 64;
            float* Xp = d_X + ((size_t)b * Ln + gl) * Hn + tile * 64;
            float a0 = stgF[(j    ) * 133 + row_l], g0 = stgF[(64 + j    ) * 133 + row_l];
            float a1 = stgF[(j + 1) * 133 + row_l], g1 = stgF[(65 + j    ) * 133 + row_l];
            float a2 = stgF[(j + 2) * 133 + row_l], g2 = stgF[(66 + j    ) * 133 + row_l];
            float a3 = stgF[(j + 3) * 133 + row_l], g3 = stgF[(67 + j    ) * 133 + row_l];
            float4 o, z;
            o.x = a0 * (1.f / (1.f + __expf(-g0)));
            o.y = a1 * (1.f / (1.f + __expf(-g1)));
            o.z = a2 * (1.f / (1.f + __expf(-g2)));
            o.w = a3 * (1.f / (1.f + __expf(-g3)));
            z = *(const float4*)(Zp + j);
            o.x += z.x; o.y += z.y; o.z += z.z; o.w += z.w;
            *(float4*)(Xp + j) = o;
        }
    }
}

// ---------------- final LayerNorm -> d_out ----------------
__global__ __launch_bounds__(256) void final_ln(
    const float* __restrict__ g, const float* __restrict__ bb, float* __restrict__ out)
{
    int lane = threadIdx.x & 31, wid = threadIdx.x >> 5;
    size_t row = (size_t)blockIdx.x * 8 + wid;
    const float* xr = d_X + row * Hn;
    float v[8], s = 0.f, q = 0.f;
#pragma unroll
    for (int k = 0; k < 8; k++) {
        v[k] = xr[k * 32 + lane];
        s += v[k]; q += v[k] * v[k];
    }
#pragma unroll
    for (int o = 16; o; o >>= 1) {
        s += __shfl_xor_sync(0xffffffffu, s, o);
        q += __shfl_xor_sync(0xffffffffu, q, o);
    }
    float m  = s * (1.f / 256.f);
    float sc = rsqrtf(q * (1.f / 256.f) - m * m + 1e-5f);
#pragma unroll
    for (int k = 0; k < 8; k++) {
        int h = k * 32 + lane;
        out[row * Hn + h] = (v[k] - m) * sc * g[h] + bb[h];
    }
}

// ---------------- launch ----------------
extern "C" void kernel_launch(void* const* d_in, const int* in_sizes, int n_in,
                              void* d_out, int out_size)
{
    const float* x       = (const float*)d_in[0];
    const float* W_in    = (const float*)d_in[1];
    const float* b_in    = (const float*)d_in[2];
    const float* ln_g    = (const float*)d_in[3];
    const float* ln_b    = (const float*)d_in[4];
    const float* log_dt  = (const float*)d_in[5];
    const float* logA_re = (const float*)d_in[6];
    const float* A_im    = (const float*)d_in[7];
    const float* Cp      = (const float*)d_in[8];
    const float* Dp      = (const float*)d_in[9];
    const float* W_glu   = (const float*)d_in[10];
    const float* b_glu   = (const float*)d_in[11];
    const float* fn_g    = (const float*)d_in[12];
    const float* fn_b    = (const float*)d_in[13];
    float* out = (float*)d_out;

    const int smem_pow = 8 * 64 * 136 * 2;                    // 139264
    const int smem_st1 = (128 * 136 + 64 * 136) * 2;          // 52224
    const int smem_st3 = (128 * 200 * 2) * 2;                 // 102400
    const int smem_glu = 128 * 133 * 4;                       // 68096 (>= mainloop 56832)
    cudaFuncSetAttribute(prep_pow, cudaFuncAttributeMaxDynamicSharedMemorySize, smem_pow);
    cudaFuncSetAttribute(st1_kernel, cudaFuncAttributeMaxDynamicSharedMemorySize, smem_st1);
    cudaFuncSetAttribute(st3_kernel, cudaFuncAttributeMaxDynamicSharedMemorySize, smem_st3);
    cudaFuncSetAttribute(glu_kernel, cudaFuncAttributeMaxDynamicSharedMemorySize, smem_glu);

    prep_ssm<<<128, 256>>>(log_dt, logA_re, A_im, Cp);
    prep_pow<<<128, 256, smem_pow>>>();
    prep_tk<<<NLn * Hn, 128>>>(Dp);
    prep_w2t<<<2048, 256>>>(W_glu, b_glu);
    in_proj<<<2500, 256>>>(x, W_in, b_in);

    for (int i = 0; i < NLn; i++) {
        dim3 gln((Ln + 31) / 32, Bn);
        ln_t_kernel<<<gln, 256>>>(i, ln_g, ln_b);
        st1_kernel<<<dim3(Mrows / 128, Hn), 256, smem_st1>>>(i);
        st2_kernel<<<512, 256>>>(i);
        st3_kernel<<<dim3(Mrows / 128, Hn), 256, smem_st3>>>(i);
        glu_kernel<<<dim3(4, LP / 128, Bn), 256, smem_glu>>>(i);
    }
    final_ln<<<(Bn * Ln) / 8, 256>>>(fn_g, fn_b, out);
}

// round 16
// speedup vs baseline: 1.3742x; 1.1188x over previous
#include <cuda_runtime.h>
#include <cuda_fp16.h>
#include <cstdint>
#include <math.h>

#define Bn   16
#define Ln   5000
#define Hn   256
#define Nn   32
#define NLn  4
#define DINn 12
#define Tc   128          // chunk length
#define Cc   40           // chunks (padded length 5120)
#define LP   5120         // padded L
#define Mrows (Bn * Cc)   // 640 chunk-rows

// ---------------- scratch (device globals; zero-initialized) ----------------
__device__ __align__(16) float  d_X  [(size_t)Bn * Ln * Hn];   // activations (B, L, H)
__device__ __align__(16) __half d_Ztr[(size_t)Bn * Hn * LP];   // LN output fp16 (B,H,Lpad), pad=0
__device__ __align__(16) __half d_Gt [(size_t)Bn * Hn * LP];   // fp16 gelu(y), (B, H, Lpad)
__device__ __align__(16) float4 d_SSMP[NLn * Hn * Nn];         // (lam_re, lam_im, 2Ct_re, 2Ct_im)
__device__ __align__(16) __half d_W2th[(size_t)NLn * 512 * Hn];// W_glu^T grouped rows, k-contig
__device__ __align__(16) float  d_b2t[NLn * 2 * Hn];
__device__ __align__(16) float  d_Q   [(size_t)Bn * Hn * Cc * 64];  // chunk state contributions
__device__ __align__(16) __half d_Pt2h[(size_t)Hn * Mrows * 64];    // fp16 chunk-start states
__device__ __align__(16) __half d_W1h[(size_t)NLn * Hn * 64 * 128]; // stage-1 B^T [n][k]
__device__ __align__(16) __half d_B3h[(size_t)NLn * Hn * 128 * 192];// stage-3 B^T [pos][k]
__device__ __align__(16) float  d_Kv[NLn * Hn * Tc];
__device__ __align__(16) float2 d_lamT[NLn * Hn * Nn];              // lambda^128

// ---------------- helpers ----------------
__device__ __forceinline__ void cp16h(__half* dst, const __half* src) {
    uint32_t d = (uint32_t)__cvta_generic_to_shared(dst);
    asm volatile("cp.async.cg.shared.global [%0], [%1], 16;\n" :: "r"(d), "l"(src));
}
__device__ __forceinline__ void cp_commit() {
    asm volatile("cp.async.commit_group;\n");
}
template <int N>
__device__ __forceinline__ void cp_wait() {
    asm volatile("cp.async.wait_group %0;\n" :: "n"(N));
}

__device__ __forceinline__ void mma_f16(float* d, const uint32_t* a, const uint32_t* b) {
    asm volatile(
        "mma.sync.aligned.m16n8k16.row.col.f32.f16.f16.f32 "
        "{%0,%1,%2,%3}, {%4,%5,%6,%7}, {%8,%9}, {%0,%1,%2,%3};\n"
        : "+f"(d[0]), "+f"(d[1]), "+f"(d[2]), "+f"(d[3])
        : "r"(a[0]), "r"(a[1]), "r"(a[2]), "r"(a[3]), "r"(b[0]), "r"(b[1]));
}

__device__ __forceinline__ void ldsm_x4(uint32_t* r, uint32_t addr) {
    asm volatile("ldmatrix.sync.aligned.m8n8.x4.shared.b16 {%0,%1,%2,%3}, [%4];"
        : "=r"(r[0]), "=r"(r[1]), "=r"(r[2]), "=r"(r[3]) : "r"(addr));
}
__device__ __forceinline__ void ldsm_x4_t(uint32_t* r, uint32_t addr) {
    asm volatile("ldmatrix.sync.aligned.m8n8.x4.trans.shared.b16 {%0,%1,%2,%3}, [%4];"
        : "=r"(r[0]), "=r"(r[1]), "=r"(r[2]), "=r"(r[3]) : "r"(addr));
}

__device__ __forceinline__ float gelu_fast(float x) {
    float t2 = 1.5957691216057308f * fmaf(0.044715f, x * x * x, x);
    return x * (1.f / (1.f + __expf(-t2)));
}

// ---------------- param prep ----------------
__global__ __launch_bounds__(256) void prep_ssm(
    const float* __restrict__ log_dt, const float* __restrict__ logA_re,
    const float* __restrict__ A_im,   const float* __restrict__ Cp)
{
    int idx = blockIdx.x * 256 + threadIdx.x;      // NL*H*N = 32768
    int i = idx / (Hn * Nn);
    int h = (idx / Nn) % Hn;
    float dt  = expf(log_dt[i * Hn + h]);
    float aRe = -expf(logA_re[idx]);
    float aIm = A_im[idx];
    float er  = expf(aRe * dt);
    float ang = aIm * dt;
    float lr = er * cosf(ang), li = er * sinf(ang);
    float nr = lr - 1.f, ni = li;
    float inv = 1.f / (aRe * aRe + aIm * aIm);
    float qr = (nr * aRe + ni * aIm) * inv;
    float qi = (ni * aRe - nr * aIm) * inv;
    float cr = Cp[2 * idx], ci = Cp[2 * idx + 1];
    float Ctr = cr * qr - ci * qi;
    float Cti = cr * qi + ci * qr;
    d_SSMP[idx] = make_float4(lr, li, 2.f * Ctr, 2.f * Cti);
}

// powers of lambda; W1 staged in smem then written coalesced
__global__ __launch_bounds__(256) void prep_pow()
{
    extern __shared__ __half ws[];                  // 8 warps x [64][136]
    int tid = threadIdx.x, wid = tid >> 5, n = tid & 31;
    int gw = blockIdx.x * 8 + wid;                  // 0..1023 = layer*256+h
    __half* W1s = ws + wid * (64 * 136);
    float4 p = d_SSMP[gw * 32 + n];
    float lr = p.x, li = p.y, tcr = p.z, tci = p.w;
    float curr = 1.f, curi = 0.f;
    __half* B3p = d_B3h + (size_t)gw * (128 * 192);
    float* Kvp = d_Kv + gw * Tc;
    for (int j = 0; j <= 128; j++) {
        if (j < 128) {
            float kr = tcr * curr - tci * curi;
            float ki = tcr * curi + tci * curr;
            W1s[n * 136 + (127 - j)]        = __float2half_rn(kr);
            W1s[(32 + n) * 136 + (127 - j)] = __float2half_rn(ki);
            float s = kr;
#pragma unroll
            for (int o = 16; o; o >>= 1) s += __shfl_xor_sync(0xffffffffu, s, o);
            if (n == 0) Kvp[j] = s;
        }
        if (j >= 1) {
            int i = j - 1;
            B3p[i * 192 + 128 + n] = __float2half_rn(curr);
            B3p[i * 192 + 160 + n] = __float2half_rn(-curi);
        }
        if (j == 128) d_lamT[gw * 32 + n] = make_float2(curr, curi);
        float nr2 = curr * lr - curi * li;
        curi = curr * li + curi * lr;
        curr = nr2;
    }
    __syncwarp();
    __half* W1p = d_W1h + (size_t)gw * (64 * 128);
#pragma unroll
    for (int it = 0; it < 32; it++) {
        int idx = it * 32 + n;
        int r = idx >> 4, g = idx & 15;
        *(uint4*)(W1p + r * 128 + g * 8) = *(const uint4*)&W1s[r * 136 + g * 8];
    }
}

// Toeplitz rows of B3 (D on diagonal); thread = j (contiguous) -> coalesced stores
__global__ __launch_bounds__(128) void prep_tk(const float* __restrict__ Dp)
{
    int gw = blockIdx.x;
    int j  = threadIdx.x;
    __shared__ float Ks[Tc];
    Ks[j] = d_Kv[gw * Tc + j];
    __syncthreads();
    float Dh = Dp[gw];
    __half* B3p = d_B3h + (size_t)gw * (128 * 192);
    for (int i = 0; i < 128; i++) {
        float v = 0.f;
        if (i >= j) v = Ks[i - j] + (i == j ? Dh : 0.f);
        B3p[i * 192 + j] = __float2half_rn(v);
    }
}

__global__ __launch_bounds__(256) void prep_w2t(
    const float* __restrict__ W_glu, const float* __restrict__ b_glu)
{
    int idx = blockIdx.x * 256 + threadIdx.x;      // NL*512*256 = 524288
    int l = idx >> 17;
    int rem = idx & 131071;
    int row = rem >> 8;
    int k = rem & 255;
    int tile = row >> 7;
    int rr = row & 127;
    int col = (rr < 64) ? (tile * 64 + rr) : (Hn + tile * 64 + (rr - 64));
    d_W2th[idx] = __float2half_rn(W_glu[((size_t)l * Hn + k) * (2 * Hn) + col]);
    if (idx < NLn * 512) {
        int l2 = idx >> 9, row2 = idx & 511;
        int t2 = row2 >> 7, r2 = row2 & 127;
        int c2 = (r2 < 64) ? (t2 * 64 + r2) : (Hn + t2 * 64 + (r2 - 64));
        d_b2t[idx] = b_glu[l2 * 512 + c2];
    }
}

// ---------------- input projection ----------------
__global__ __launch_bounds__(256) void in_proj(
    const float* __restrict__ x, const float* __restrict__ W, const float* __restrict__ bias)
{
    __shared__ float xs[32][DINn];
    int tid = threadIdx.x;
    int r0 = blockIdx.x * 32;
    for (int t = tid; t < 32 * DINn; t += 256)
        xs[t / DINn][t % DINn] = x[(size_t)r0 * DINn + t];
    float w[DINn];
#pragma unroll
    for (int k = 0; k < DINn; k++) w[k] = W[k * Hn + tid];
    float bv = bias[tid];
    __syncthreads();
#pragma unroll 4
    for (int r = 0; r < 32; r++) {
        float a = bv;
#pragma unroll
        for (int k = 0; k < DINn; k++) a = fmaf(xs[r][k], w[k], a);
        d_X[((size_t)(r0 + r)) * Hn + tid] = a;
    }
}

// ---- LayerNorm: writes ONLY Ztr (fp16 transposed) — residual read back from Ztr ----
__global__ __launch_bounds__(256) void ln_t_kernel(
    int layer, const float* __restrict__ ln_g, const float* __restrict__ ln_b)
{
    __shared__ float tile[32][257];
    __shared__ float mu[32], sc[32];
    int b  = blockIdx.y;
    int l0 = blockIdx.x * 32;
    int tid = threadIdx.x, lane = tid & 31, wid = tid >> 5;
    const float* Xb = d_X + (size_t)b * Ln * Hn;
#pragma unroll
    for (int r = 0; r < 32; r++) {
        int l = l0 + r;
        tile[r][tid] = (l < Ln) ? Xb[(size_t)l * Hn + tid] : 0.f;
    }
    __syncthreads();
#pragma unroll
    for (int rr = 0; rr < 4; rr++) {
        int r = wid * 4 + rr;
        float s = 0.f, q = 0.f;
#pragma unroll
        for (int k = 0; k < 8; k++) {
            float v = tile[r][k * 32 + lane];
            s += v; q += v * v;
        }
#pragma unroll
        for (int o = 16; o; o >>= 1) {
            s += __shfl_xor_sync(0xffffffffu, s, o);
            q += __shfl_xor_sync(0xffffffffu, q, o);
        }
        if (lane == 0) {
            float m = s * (1.f / 256.f);
            float v = q * (1.f / 256.f) - m * m;
            mu[r] = m;
            sc[r] = rsqrtf(v + 1e-5f);
        }
    }
    __syncthreads();
    const float* g  = ln_g + layer * Hn;
    const float* bb = ln_b + layer * Hn;
    __half* Zrb = d_Ztr + (size_t)b * Hn * LP;
    int l = l0 + lane;
    if (l < Ln) {
        float m = mu[lane], s = sc[lane];
#pragma unroll
        for (int hi = 0; hi < 32; hi++) {
            int h = wid * 32 + hi;
            float zv = (tile[lane][h] - m) * s * g[h] + bb[h];
            Zrb[(size_t)h * LP + l] = __float2half_rn(zv);
        }
    }
}

// ---- stage 1: q = u_chunk @ W1 (M=640,N=64,K=128), single-shot resident smem -------
__global__ __launch_bounds__(256) void st1_kernel(int layer)
{
    extern __shared__ __half smh[];
    __half* As = smh;                      // [128][136]
    __half* Bs = smh + 128 * 136;          // [64][136]
    uint32_t sbase;
    asm("{ .reg .u64 t; cvta.to.shared.u64 t, %1; cvt.u32.u64 %0, t; }" : "=r"(sbase) : "l"(smh));
    int h  = blockIdx.y;
    int m0 = blockIdx.x * 128;
    int tid = threadIdx.x, lane = tid & 31, wid = tid >> 5;
    int wm = wid & 3, wn = wid >> 2;
    int tg = lane & 3, gp = lane >> 2;
    int grp = lane >> 3, lr = lane & 7;

    for (int i = 0; i < 8; i++) {
        int idx = tid + i * 256;
        int r = idx >> 4, g = idx & 15;
        int gm = m0 + r;
        int bbA = gm / Cc, ccA = gm % Cc;
        cp16h(As + r * 136 + g * 8,
              d_Ztr + ((size_t)(bbA * Hn + h)) * LP + ccA * Tc + g * 8);
    }
    const __half* W1p = d_W1h + (size_t)(layer * Hn + h) * (64 * 128);
    for (int i = 0; i < 4; i++) {
        int idx = tid + i * 256;
        int r = idx >> 4, g = idx & 15;
        cp16h(Bs + r * 136 + g * 8, W1p + r * 128 + g * 8);
    }
    cp_commit();
    cp_wait<0>();
    __syncthreads();

    float acc[2][4][4] = {};
    uint32_t aOff = (uint32_t)(((wm * 32 + (grp & 1) * 8 + lr) * 136 + (grp >> 1) * 8) * 2);
    uint32_t bOff = (uint32_t)((128 * 136 + (wn * 32 + (grp & 1) * 8 + lr) * 136 + (grp >> 1) * 8) * 2);
#pragma unroll
    for (int k2 = 0; k2 < 128; k2 += 16) {
        uint32_t af[2][4], bf[4][2];
#pragma unroll
        for (int mi = 0; mi < 2; mi++)
            ldsm_x4(af[mi], sbase + aOff + (uint32_t)((mi * 16 * 136 + k2) * 2));
#pragma unroll
        for (int nj = 0; nj < 2; nj++) {
            uint32_t q[4];
            ldsm_x4(q, sbase + bOff + (uint32_t)((nj * 16 * 136 + k2) * 2));
            bf[nj * 2][0] = q[0]; bf[nj * 2 + 1][0] = q[1];
            bf[nj * 2][1] = q[2]; bf[nj * 2 + 1][1] = q[3];
        }
#pragma unroll
        for (int mi = 0; mi < 2; mi++)
#pragma unroll
            for (int ni = 0; ni < 4; ni++)
                mma_f16(acc[mi][ni], af[mi], bf[ni]);
    }

#pragma unroll
    for (int mi = 0; mi < 2; mi++) {
#pragma unroll
        for (int ni = 0; ni < 4; ni++) {
            int n = wn * 32 + ni * 8 + tg * 2;
#pragma unroll
            for (int hf = 0; hf < 2; hf++) {
                int grow = m0 + wm * 32 + mi * 16 + gp + hf * 8;
                int b2 = grow / Cc, c2 = grow % Cc;
                size_t addr = ((size_t)(b2 * Hn + h) * Cc + c2) * 64 + n;
                d_Q[addr]     = acc[mi][ni][hf * 2];
                d_Q[addr + 1] = acc[mi][ni][hf * 2 + 1];
            }
        }
    }
}

// ---------------- stage 2: serial state pass -> Pt2h [h][m][64] fp16 ----------------
__global__ __launch_bounds__(256) void st2_kernel(int layer)
{
    int t = blockIdx.x * 256 + threadIdx.x;   // 131072
    int n = t & 31;
    int bh = t >> 5;
    int h = bh & 255, b = bh >> 8;
    float2 lt = d_lamT[(layer * Hn + h) * 32 + n];
    const float* qp = d_Q + (size_t)bh * (Cc * 64);
    __half* pp = d_Pt2h + ((size_t)h * Mrows + b * Cc) * 64;
    float pr = 0.f, pi = 0.f;
    for (int c = 0; c < Cc; c++) {
        pp[c * 64 + n]      = __float2half_rn(pr);
        pp[c * 64 + 32 + n] = __float2half_rn(pi);
        float qr = qp[c * 64 + n], qi = qp[c * 64 + 32 + n];
        float prn = fmaf(lt.x, pr, fmaf(-lt.y, pi, qr));
        pi        = fmaf(lt.y, pr, fmaf( lt.x, pi, qi));
        pr = prn;
    }
}

// ---- stage 3: y = [u|p] @ B3^T, gelu -> Gt fp16, single-shot resident smem ---------
__global__ __launch_bounds__(256) void st3_kernel(int layer)
{
    extern __shared__ __half smh[];
    __half* As = smh;                      // [128][200] (U 0..127 | P 128..191 | pad)
    __half* Bs = smh + 128 * 200;          // [128][200]
    uint32_t sbase;
    asm("{ .reg .u64 t; cvta.to.shared.u64 t, %1; cvt.u32.u64 %0, t; }" : "=r"(sbase) : "l"(smh));
    int h  = blockIdx.y;
    int m0 = blockIdx.x * 128;
    int tid = threadIdx.x, lane = tid & 31, wid = tid >> 5;
    int wm = wid & 3, wn = wid >> 2;
    int tg = lane & 3, gp = lane >> 2;
    int grp = lane >> 3, lr = lane & 7;

    for (int i = 0; i < 12; i++) {
        int idx = tid + i * 256;
        int r = idx / 24, g = idx - r * 24;
        int gm = m0 + r;
        int bbA = gm / Cc, ccA = gm % Cc;
        const __half* src;
        if (g < 16)
            src = d_Ztr + ((size_t)(bbA * Hn + h)) * LP + ccA * Tc + g * 8;
        else
            src = d_Pt2h + ((size_t)h * Mrows + gm) * 64 + (g - 16) * 8;
        cp16h(As + r * 200 + g * 8, src);
    }
    const __half* B3p = d_B3h + (size_t)(layer * Hn + h) * (128 * 192);
    for (int i = 0; i < 12; i++) {
        int idx = tid + i * 256;
        int r = idx / 24, g = idx - r * 24;
        cp16h(Bs + r * 200 + g * 8, B3p + r * 192 + g * 8);
    }
    cp_commit();
    cp_wait<0>();
    __syncthreads();

    float acc[2][8][4] = {};
    uint32_t aOff = (uint32_t)(((wm * 32 + (grp & 1) * 8 + lr) * 200 + (grp >> 1) * 8) * 2);
    uint32_t bOff = (uint32_t)((128 * 200 + (wn * 64 + (grp & 1) * 8 + lr) * 200 + (grp >> 1) * 8) * 2);
#pragma unroll
    for (int k2 = 0; k2 < 192; k2 += 16) {
        uint32_t af[2][4], bf[8][2];
#pragma unroll
        for (int mi = 0; mi < 2; mi++)
            ldsm_x4(af[mi], sbase + aOff + (uint32_t)((mi * 16 * 200 + k2) * 2));
#pragma unroll
        for (int nj = 0; nj < 4; nj++) {
            uint32_t q[4];
            ldsm_x4(q, sbase + bOff + (uint32_t)((nj * 16 * 200 + k2) * 2));
            bf[nj * 2][0] = q[0]; bf[nj * 2 + 1][0] = q[1];
            bf[nj * 2][1] = q[2]; bf[nj * 2 + 1][1] = q[3];
        }
#pragma unroll
        for (int mi = 0; mi < 2; mi++)
#pragma unroll
            for (int ni = 0; ni < 8; ni++)
                mma_f16(acc[mi][ni], af[mi], bf[ni]);
    }

    __syncthreads();
    __half* stg = smh;                     // [128][136]
#pragma unroll
    for (int mi = 0; mi < 2; mi++) {
#pragma unroll
        for (int ni = 0; ni < 8; ni++) {
            int i = wn * 64 + ni * 8 + tg * 2;
#pragma unroll
            for (int hf = 0; hf < 2; hf++) {
                int ml = wm * 32 + mi * 16 + gp + hf * 8;
                __half2 v = __floats2half2_rn(gelu_fast(acc[mi][ni][hf * 2]),
                                              gelu_fast(acc[mi][ni][hf * 2 + 1]));
                *(__half2*)&stg[ml * 136 + i] = v;
            }
        }
    }
    __syncthreads();
#pragma unroll
    for (int it = 0; it < 8; it++) {
        int idx = tid + it * 256;
        int row = idx >> 4, g = idx & 15;
        int grow = m0 + row;
        int b2 = grow / Cc, c2 = grow % Cc;
        uint4 v = *(const uint4*)&stg[row * 136 + g * 8];
        *(uint4*)(d_Gt + ((size_t)(b2 * Hn + h)) * LP + c2 * Tc + g * 8) = v;
    }
}

// -------- GLU GEMM fp16 (ldmatrix, direct Gt): D[ch 128][l 128] = W2t x Gt^T --------
// Residual staged from Ztr (fp16, coalesced rows) in smem; epilogue reads transposed.
__global__ __launch_bounds__(256) void glu_kernel(int layer)
{
    extern __shared__ __half smh[];
    // mainloop: A bufs 3x[128][40] @0 ; B bufs 3x[32][136] @15360 (ends 28416 halves)
    // epilogue: stgF floats [128][133] @0 (34048 halves) ; Zs [64][136] @34048 halves
    __shared__ float biasS[128];
    uint32_t sbase;
    asm("{ .reg .u64 t; cvta.to.shared.u64 t, %1; cvt.u32.u64 %0, t; }" : "=r"(sbase) : "l"(smh));
    const int tile = blockIdx.x;           // channel group 0..3
    const int l0   = blockIdx.y * 128;
    const int b    = blockIdx.z;
    const int m0   = tile * 128;
    int tid = threadIdx.x, lane = tid & 31, wid = tid >> 5;
    int wm = wid & 3, wn = wid >> 2;       // warp tile: 32 m x 64 n
    int tg = lane & 3, gp = lane >> 2;

    if (tid < 128) biasS[tid] = d_b2t[layer * 512 + m0 + tid];

    __half* Zs = smh + 34048;              // [64][136] residual tile

    int rA = tid >> 1, gA = (tid & 1) * 2;
    const __half* Wp = d_W2th + (size_t)(layer * 512 + m0 + rA) * 256;
    int rB = tid >> 3, gB = tid & 7;       // B: 32 k-rows x 16 granules, 2 per thread
    const __half* Gp = d_Gt + ((size_t)(b * Hn + rB)) * LP + l0;

    float acc[2][8][4] = {};

    auto fill = [&](int s) {
        int kt = s * 32;
        __half* dA = smh + (s % 3) * (128 * 40);
        cp16h(dA + rA * 40 + gA * 8, Wp + kt + gA * 8);
        cp16h(dA + rA * 40 + (gA + 1) * 8, Wp + kt + (gA + 1) * 8);
        __half* dB = smh + 15360 + (s % 3) * (32 * 136);
        const __half* src = Gp + (size_t)kt * LP;
        cp16h(dB + rB * 136 + gB * 8, src + gB * 8);
        cp16h(dB + rB * 136 + (gB + 8) * 8, src + (gB + 8) * 8);
    };

    int grp = lane >> 3, lr = lane & 7;
    uint32_t aOff = (uint32_t)(((wm * 32 + (grp & 1) * 8 + lr) * 40 + (grp >> 1) * 8) * 2);
    uint32_t bOff = (uint32_t)((((grp & 1) * 8 + lr) * 136 + wn * 64 + (grp >> 1) * 8) * 2);

    fill(0);
    // residual tile: 64 h-rows x 16 granules, fully coalesced; completes with group 0
    for (int i = 0; i < 4; i++) {
        int idx = tid + i * 256;
        int r = idx >> 4, g = idx & 15;
        cp16h(Zs + r * 136 + g * 8,
              d_Ztr + ((size_t)(b * Hn + tile * 64 + r)) * LP + l0 + g * 8);
    }
    cp_commit();
    fill(1); cp_commit();
#pragma unroll
    for (int s = 0; s < 8; s++) {
        if (s < 7) cp_wait<1>(); else cp_wait<0>();
        __syncthreads();
        if (s + 2 < 8) { fill(s + 2); cp_commit(); }
        uint32_t aBuf = sbase + (uint32_t)((s % 3) * (128 * 40) * 2);
        uint32_t bBuf = sbase + (uint32_t)((15360 + (s % 3) * (32 * 136)) * 2);
#pragma unroll
        for (int k2 = 0; k2 < 32; k2 += 16) {
            uint32_t af[2][4], bf[8][2];
#pragma unroll
            for (int mi = 0; mi < 2; mi++)
                ldsm_x4(af[mi], aBuf + aOff + (uint32_t)((mi * 16 * 40 + k2) * 2));
#pragma unroll
            for (int nj = 0; nj < 4; nj++) {
                uint32_t q[4];
                ldsm_x4_t(q, bBuf + bOff + (uint32_t)((k2 * 136 + nj * 16) * 2));
                bf[nj * 2][0] = q[0]; bf[nj * 2][1] = q[1];
                bf[nj * 2 + 1][0] = q[2]; bf[nj * 2 + 1][1] = q[3];
            }
#pragma unroll
            for (int mi = 0; mi < 2; mi++)
#pragma unroll
                for (int ni = 0; ni < 8; ni++)
                    mma_f16(acc[mi][ni], af[mi], bf[ni]);
        }
    }

    // stage C[ch][l] (+bias) in fp32, then GLU + fp16 residual from Zs, coalesced X
    __syncthreads();
    float* stgF = (float*)smh;             // [128 ch][133 l]
#pragma unroll
    for (int mi = 0; mi < 2; mi++) {
#pragma unroll
        for (int hf = 0; hf < 2; hf++) {
            int row = wm * 32 + mi * 16 + gp + hf * 8;
            float bv = biasS[row];
#pragma unroll
            for (int ni = 0; ni < 8; ni++) {
                int col = wn * 64 + ni * 8 + tg * 2;
                stgF[row * 133 + col]     = acc[mi][ni][hf * 2]     + bv;
                stgF[row * 133 + col + 1] = acc[mi][ni][hf * 2 + 1] + bv;
            }
        }
    }
    __syncthreads();
#pragma unroll
    for (int it = 0; it < 8; it++) {
        int idx = tid + it * 256;          // 2048 tasks = 128 l-rows x 16 float4
        int row_l = idx >> 4;
        int j = (idx & 15) * 4;            // channel within 64
        int gl = l0 + row_l;
        if (gl < Ln) {
            float* Xp = d_X + ((size_t)b * Ln + gl) * Hn + tile * 64;
            float a0 = stgF[(j    ) * 133 + row_l], g0 = stgF[(64 + j    ) * 133 + row_l];
            float a1 = stgF[(j + 1) * 133 + row_l], g1 = stgF[(65 + j    ) * 133 + row_l];
            float a2 = stgF[(j + 2) * 133 + row_l], g2 = stgF[(66 + j    ) * 133 + row_l];
            float a3 = stgF[(j + 3) * 133 + row_l], g3 = stgF[(67 + j    ) * 133 + row_l];
            float4 o;
            o.x = a0 * (1.f / (1.f + __expf(-g0)));
            o.y = a1 * (1.f / (1.f + __expf(-g1)));
            o.z = a2 * (1.f / (1.f + __expf(-g2)));
            o.w = a3 * (1.f / (1.f + __expf(-g3)));
            o.x += __half2float(Zs[(j    ) * 136 + row_l]);
            o.y += __half2float(Zs[(j + 1) * 136 + row_l]);
            o.z += __half2float(Zs[(j + 2) * 136 + row_l]);
            o.w += __half2float(Zs[(j + 3) * 136 + row_l]);
            *(float4*)(Xp + j) = o;
        }
    }
}

// ---------------- final LayerNorm -> d_out ----------------
__global__ __launch_bounds__(256) void final_ln(
    const float* __restrict__ g, const float* __restrict__ bb, float* __restrict__ out)
{
    int lane = threadIdx.x & 31, wid = threadIdx.x >> 5;
    size_t row = (size_t)blockIdx.x * 8 + wid;
    const float* xr = d_X + row * Hn;
    float v[8], s = 0.f, q = 0.f;
#pragma unroll
    for (int k = 0; k < 8; k++) {
        v[k] = xr[k * 32 + lane];
        s += v[k]; q += v[k] * v[k];
    }
#pragma unroll
    for (int o = 16; o; o >>= 1) {
        s += __shfl_xor_sync(0xffffffffu, s, o);
        q += __shfl_xor_sync(0xffffffffu, q, o);
    }
    float m  = s * (1.f / 256.f);
    float sc = rsqrtf(q * (1.f / 256.f) - m * m + 1e-5f);
#pragma unroll
    for (int k = 0; k < 8; k++) {
        int h = k * 32 + lane;
        out[row * Hn + h] = (v[k] - m) * sc * g[h] + bb[h];
    }
}

// ---------------- launch ----------------
extern "C" void kernel_launch(void* const* d_in, const int* in_sizes, int n_in,
                              void* d_out, int out_size)
{
    const float* x       = (const float*)d_in[0];
    const float* W_in    = (const float*)d_in[1];
    const float* b_in    = (const float*)d_in[2];
    const float* ln_g    = (const float*)d_in[3];
    const float* ln_b    = (const float*)d_in[4];
    const float* log_dt  = (const float*)d_in[5];
    const float* logA_re = (const float*)d_in[6];
    const float* A_im    = (const float*)d_in[7];
    const float* Cp      = (const float*)d_in[8];
    const float* Dp      = (const float*)d_in[9];
    const float* W_glu   = (const float*)d_in[10];
    const float* b_glu   = (const float*)d_in[11];
    const float* fn_g    = (const float*)d_in[12];
    const float* fn_b    = (const float*)d_in[13];
    float* out = (float*)d_out;

    const int smem_pow = 8 * 64 * 136 * 2;                    // 139264
    const int smem_st1 = (128 * 136 + 64 * 136) * 2;          // 52224
    const int smem_st3 = (128 * 200 * 2) * 2;                 // 102400
    const int smem_glu = (34048 + 64 * 136) * 2;              // 85504
    cudaFuncSetAttribute(prep_pow, cudaFuncAttributeMaxDynamicSharedMemorySize, smem_pow);
    cudaFuncSetAttribute(st1_kernel, cudaFuncAttributeMaxDynamicSharedMemorySize, smem_st1);
    cudaFuncSetAttribute(st3_kernel, cudaFuncAttributeMaxDynamicSharedMemorySize, smem_st3);
    cudaFuncSetAttribute(glu_kernel, cudaFuncAttributeMaxDynamicSharedMemorySize, smem_glu);

    prep_ssm<<<128, 256>>>(log_dt, logA_re, A_im, Cp);
    prep_pow<<<128, 256, smem_pow>>>();
    prep_tk<<<NLn * Hn, 128>>>(Dp);
    prep_w2t<<<2048, 256>>>(W_glu, b_glu);
    in_proj<<<2500, 256>>>(x, W_in, b_in);

    for (int i = 0; i < NLn; i++) {
        dim3 gln((Ln + 31) / 32, Bn);
        ln_t_kernel<<<gln, 256>>>(i, ln_g, ln_b);
        st1_kernel<<<dim3(Mrows / 128, Hn), 256, smem_st1>>>(i);
        st2_kernel<<<512, 256>>>(i);
        st3_kernel<<<dim3(Mrows / 128, Hn), 256, smem_st3>>>(i);
        glu_kernel<<<dim3(4, LP / 128, Bn), 256, smem_glu>>>(i);
    }
    final_ln<<<(Bn * Ln) / 8, 256>>>(fn_g, fn_b, out);
}

// round 17
// speedup vs baseline: 1.4154x; 1.0299x over previous
#include <cuda_runtime.h>
#include <cuda_fp16.h>
#include <cstdint>
#include <math.h>

#define Bn   16
#define Ln   5000
#define Hn   256
#define Nn   32
#define NLn  4
#define DINn 12
#define Tc   128          // chunk length
#define Cc   40           // chunks (padded length 5120)
#define LP   5120         // padded L
#define Mrows (Bn * Cc)   // 640 chunk-rows

// ---------------- scratch (device globals; zero-initialized) ----------------
__device__ __align__(16) __half d_Xh [(size_t)Bn * Ln * Hn];   // activations fp16 (B, L, H)
__device__ __align__(16) __half d_Ztr[(size_t)Bn * Hn * LP];   // LN output fp16 (B,H,Lpad), pad=0
__device__ __align__(16) __half d_Gt [(size_t)Bn * Hn * LP];   // fp16 gelu(y), (B, H, Lpad)
__device__ __align__(16) float4 d_SSMP[NLn * Hn * Nn];         // (lam_re, lam_im, 2Ct_re, 2Ct_im)
__device__ __align__(16) __half d_W2th[(size_t)NLn * 512 * Hn];// W_glu^T grouped rows, k-contig
__device__ __align__(16) float  d_b2t[NLn * 2 * Hn];
__device__ __align__(16) float  d_Q   [(size_t)Bn * Hn * Cc * 64];  // chunk state contributions
__device__ __align__(16) __half d_Pt2h[(size_t)Hn * Mrows * 64];    // fp16 chunk-start states
__device__ __align__(16) __half d_W1h[(size_t)NLn * Hn * 64 * 128]; // stage-1 B^T [n][k]
__device__ __align__(16) __half d_B3h[(size_t)NLn * Hn * 128 * 192];// stage-3 B^T [pos][k]
__device__ __align__(16) float  d_Kv[NLn * Hn * Tc];
__device__ __align__(16) float2 d_lamT[NLn * Hn * Nn];              // lambda^128

// ---------------- helpers ----------------
__device__ __forceinline__ void cp16h(__half* dst, const __half* src) {
    uint32_t d = (uint32_t)__cvta_generic_to_shared(dst);
    asm volatile("cp.async.cg.shared.global [%0], [%1], 16;\n" :: "r"(d), "l"(src));
}
__device__ __forceinline__ void cp_commit() {
    asm volatile("cp.async.commit_group;\n");
}
template <int N>
__device__ __forceinline__ void cp_wait() {
    asm volatile("cp.async.wait_group %0;\n" :: "n"(N));
}

__device__ __forceinline__ void mma_f16(float* d, const uint32_t* a, const uint32_t* b) {
    asm volatile(
        "mma.sync.aligned.m16n8k16.row.col.f32.f16.f16.f32 "
        "{%0,%1,%2,%3}, {%4,%5,%6,%7}, {%8,%9}, {%0,%1,%2,%3};\n"
        : "+f"(d[0]), "+f"(d[1]), "+f"(d[2]), "+f"(d[3])
        : "r"(a[0]), "r"(a[1]), "r"(a[2]), "r"(a[3]), "r"(b[0]), "r"(b[1]));
}

__device__ __forceinline__ void ldsm_x4(uint32_t* r, uint32_t addr) {
    asm volatile("ldmatrix.sync.aligned.m8n8.x4.shared.b16 {%0,%1,%2,%3}, [%4];"
        : "=r"(r[0]), "=r"(r[1]), "=r"(r[2]), "=r"(r[3]) : "r"(addr));
}
__device__ __forceinline__ void ldsm_x4_t(uint32_t* r, uint32_t addr) {
    asm volatile("ldmatrix.sync.aligned.m8n8.x4.trans.shared.b16 {%0,%1,%2,%3}, [%4];"
        : "=r"(r[0]), "=r"(r[1]), "=r"(r[2]), "=r"(r[3]) : "r"(addr));
}

__device__ __forceinline__ float gelu_fast(float x) {
    float t2 = 1.5957691216057308f * fmaf(0.044715f, x * x * x, x);
    return x * (1.f / (1.f + __expf(-t2)));
}

// ---------------- param prep ----------------
__global__ __launch_bounds__(256) void prep_ssm(
    const float* __restrict__ log_dt, const float* __restrict__ logA_re,
    const float* __restrict__ A_im,   const float* __restrict__ Cp)
{
    int idx = blockIdx.x * 256 + threadIdx.x;      // NL*H*N = 32768
    int i = idx / (Hn * Nn);
    int h = (idx / Nn) % Hn;
    float dt  = expf(log_dt[i * Hn + h]);
    float aRe = -expf(logA_re[idx]);
    float aIm = A_im[idx];
    float er  = expf(aRe * dt);
    float ang = aIm * dt;
    float lr = er * cosf(ang), li = er * sinf(ang);
    float nr = lr - 1.f, ni = li;
    float inv = 1.f / (aRe * aRe + aIm * aIm);
    float qr = (nr * aRe + ni * aIm) * inv;
    float qi = (ni * aRe - nr * aIm) * inv;
    float cr = Cp[2 * idx], ci = Cp[2 * idx + 1];
    float Ctr = cr * qr - ci * qi;
    float Cti = cr * qi + ci * qr;
    d_SSMP[idx] = make_float4(lr, li, 2.f * Ctr, 2.f * Cti);
}

// powers of lambda; W1 staged in smem then written coalesced
__global__ __launch_bounds__(256) void prep_pow()
{
    extern __shared__ __half ws[];                  // 8 warps x [64][136]
    int tid = threadIdx.x, wid = tid >> 5, n = tid & 31;
    int gw = blockIdx.x * 8 + wid;                  // 0..1023 = layer*256+h
    __half* W1s = ws + wid * (64 * 136);
    float4 p = d_SSMP[gw * 32 + n];
    float lr = p.x, li = p.y, tcr = p.z, tci = p.w;
    float curr = 1.f, curi = 0.f;
    __half* B3p = d_B3h + (size_t)gw * (128 * 192);
    float* Kvp = d_Kv + gw * Tc;
    for (int j = 0; j <= 128; j++) {
        if (j < 128) {
            float kr = tcr * curr - tci * curi;
            float ki = tcr * curi + tci * curr;
            W1s[n * 136 + (127 - j)]        = __float2half_rn(kr);
            W1s[(32 + n) * 136 + (127 - j)] = __float2half_rn(ki);
            float s = kr;
#pragma unroll
            for (int o = 16; o; o >>= 1) s += __shfl_xor_sync(0xffffffffu, s, o);
            if (n == 0) Kvp[j] = s;
        }
        if (j >= 1) {
            int i = j - 1;
            B3p[i * 192 + 128 + n] = __float2half_rn(curr);
            B3p[i * 192 + 160 + n] = __float2half_rn(-curi);
        }
        if (j == 128) d_lamT[gw * 32 + n] = make_float2(curr, curi);
        float nr2 = curr * lr - curi * li;
        curi = curr * li + curi * lr;
        curr = nr2;
    }
    __syncwarp();
    __half* W1p = d_W1h + (size_t)gw * (64 * 128);
#pragma unroll
    for (int it = 0; it < 32; it++) {
        int idx = it * 32 + n;
        int r = idx >> 4, g = idx & 15;
        *(uint4*)(W1p + r * 128 + g * 8) = *(const uint4*)&W1s[r * 136 + g * 8];
    }
}

// Toeplitz rows of B3 (D on diagonal); thread = j (contiguous) -> coalesced stores
__global__ __launch_bounds__(128) void prep_tk(const float* __restrict__ Dp)
{
    int gw = blockIdx.x;
    int j  = threadIdx.x;
    __shared__ float Ks[Tc];
    Ks[j] = d_Kv[gw * Tc + j];
    __syncthreads();
    float Dh = Dp[gw];
    __half* B3p = d_B3h + (size_t)gw * (128 * 192);
    for (int i = 0; i < 128; i++) {
        float v = 0.f;
        if (i >= j) v = Ks[i - j] + (i == j ? Dh : 0.f);
        B3p[i * 192 + j] = __float2half_rn(v);
    }
}

__global__ __launch_bounds__(256) void prep_w2t(
    const float* __restrict__ W_glu, const float* __restrict__ b_glu)
{
    int idx = blockIdx.x * 256 + threadIdx.x;      // NL*512*256 = 524288
    int l = idx >> 17;
    int rem = idx & 131071;
    int row = rem >> 8;
    int k = rem & 255;
    int tile = row >> 7;
    int rr = row & 127;
    int col = (rr < 64) ? (tile * 64 + rr) : (Hn + tile * 64 + (rr - 64));
    d_W2th[idx] = __float2half_rn(W_glu[((size_t)l * Hn + k) * (2 * Hn) + col]);
    if (idx < NLn * 512) {
        int l2 = idx >> 9, row2 = idx & 511;
        int t2 = row2 >> 7, r2 = row2 & 127;
        int c2 = (r2 < 64) ? (t2 * 64 + r2) : (Hn + t2 * 64 + (r2 - 64));
        d_b2t[idx] = b_glu[l2 * 512 + c2];
    }
}

// ---- fused input projection + layer-0 LayerNorm -> Ztr (X0 never materialized) ----
__global__ __launch_bounds__(256) void in_proj_ln(
    const float* __restrict__ x, const float* __restrict__ W, const float* __restrict__ bias,
    const float* __restrict__ ln_g, const float* __restrict__ ln_b)
{
    __shared__ float xs[32][DINn];
    __shared__ float tile[32][257];
    __shared__ float mu[32], sc[32];
    int b  = blockIdx.y;
    int l0 = blockIdx.x * 32;
    int tid = threadIdx.x, lane = tid & 31, wid = tid >> 5;
    for (int t = tid; t < 32 * DINn; t += 256) {
        int r = t / DINn, k = t % DINn;
        int l = l0 + r;
        xs[r][k] = (l < Ln) ? x[((size_t)b * Ln + l) * DINn + k] : 0.f;
    }
    float w[DINn];
#pragma unroll
    for (int k = 0; k < DINn; k++) w[k] = W[k * Hn + tid];
    float bv = bias[tid];
    __syncthreads();
#pragma unroll 4
    for (int r = 0; r < 32; r++) {
        float a = bv;
#pragma unroll
        for (int k = 0; k < DINn; k++) a = fmaf(xs[r][k], w[k], a);
        tile[r][tid] = a;
    }
    __syncthreads();
#pragma unroll
    for (int rr = 0; rr < 4; rr++) {
        int r = wid * 4 + rr;
        float s = 0.f, q = 0.f;
#pragma unroll
        for (int k = 0; k < 8; k++) {
            float v = tile[r][k * 32 + lane];
            s += v; q += v * v;
        }
#pragma unroll
        for (int o = 16; o; o >>= 1) {
            s += __shfl_xor_sync(0xffffffffu, s, o);
            q += __shfl_xor_sync(0xffffffffu, q, o);
        }
        if (lane == 0) {
            float m = s * (1.f / 256.f);
            float v = q * (1.f / 256.f) - m * m;
            mu[r] = m;
            sc[r] = rsqrtf(v + 1e-5f);
        }
    }
    __syncthreads();
    __half* Zrb = d_Ztr + (size_t)b * Hn * LP;
    int l = l0 + lane;
    if (l < Ln) {
        float m = mu[lane], s = sc[lane];
#pragma unroll
        for (int hi = 0; hi < 32; hi++) {
            int h = wid * 32 + hi;
            float zv = (tile[lane][h] - m) * s * ln_g[h] + ln_b[h];
            Zrb[(size_t)h * LP + l] = __float2half_rn(zv);
        }
    }
}

// ---- LayerNorm (layers 1..3): reads fp16 Xh, writes Ztr fp16 transposed -----------
__global__ __launch_bounds__(256) void ln_t_kernel(
    int layer, const float* __restrict__ ln_g, const float* __restrict__ ln_b)
{
    __shared__ float tile[32][257];
    __shared__ float mu[32], sc[32];
    int b  = blockIdx.y;
    int l0 = blockIdx.x * 32;
    int tid = threadIdx.x, lane = tid & 31, wid = tid >> 5;
    const __half* Xb = d_Xh + (size_t)b * Ln * Hn;
#pragma unroll
    for (int r = 0; r < 32; r++) {
        int l = l0 + r;
        tile[r][tid] = (l < Ln) ? __half2float(Xb[(size_t)l * Hn + tid]) : 0.f;
    }
    __syncthreads();
#pragma unroll
    for (int rr = 0; rr < 4; rr++) {
        int r = wid * 4 + rr;
        float s = 0.f, q = 0.f;
#pragma unroll
        for (int k = 0; k < 8; k++) {
            float v = tile[r][k * 32 + lane];
            s += v; q += v * v;
        }
#pragma unroll
        for (int o = 16; o; o >>= 1) {
            s += __shfl_xor_sync(0xffffffffu, s, o);
            q += __shfl_xor_sync(0xffffffffu, q, o);
        }
        if (lane == 0) {
            float m = s * (1.f / 256.f);
            float v = q * (1.f / 256.f) - m * m;
            mu[r] = m;
            sc[r] = rsqrtf(v + 1e-5f);
        }
    }
    __syncthreads();
    const float* g  = ln_g + layer * Hn;
    const float* bb = ln_b + layer * Hn;
    __half* Zrb = d_Ztr + (size_t)b * Hn * LP;
    int l = l0 + lane;
    if (l < Ln) {
        float m = mu[lane], s = sc[lane];
#pragma unroll
        for (int hi = 0; hi < 32; hi++) {
            int h = wid * 32 + hi;
            float zv = (tile[lane][h] - m) * s * g[h] + bb[h];
            Zrb[(size_t)h * LP + l] = __float2half_rn(zv);
        }
    }
}

// ---- stage 1: q = u_chunk @ W1 (M=640,N=64,K=128), single-shot resident smem -------
__global__ __launch_bounds__(256) void st1_kernel(int layer)
{
    extern __shared__ __half smh[];
    __half* As = smh;                      // [128][136]
    __half* Bs = smh + 128 * 136;          // [64][136]
    uint32_t sbase;
    asm("{ .reg .u64 t; cvta.to.shared.u64 t, %1; cvt.u32.u64 %0, t; }" : "=r"(sbase) : "l"(smh));
    int h  = blockIdx.y;
    int m0 = blockIdx.x * 128;
    int tid = threadIdx.x, lane = tid & 31, wid = tid >> 5;
    int wm = wid & 3, wn = wid >> 2;
    int tg = lane & 3, gp = lane >> 2;
    int grp = lane >> 3, lr = lane & 7;

    for (int i = 0; i < 8; i++) {
        int idx = tid + i * 256;
        int r = idx >> 4, g = idx & 15;
        int gm = m0 + r;
        int bbA = gm / Cc, ccA = gm % Cc;
        cp16h(As + r * 136 + g * 8,
              d_Ztr + ((size_t)(bbA * Hn + h)) * LP + ccA * Tc + g * 8);
    }
    const __half* W1p = d_W1h + (size_t)(layer * Hn + h) * (64 * 128);
    for (int i = 0; i < 4; i++) {
        int idx = tid + i * 256;
        int r = idx >> 4, g = idx & 15;
        cp16h(Bs + r * 136 + g * 8, W1p + r * 128 + g * 8);
    }
    cp_commit();
    cp_wait<0>();
    __syncthreads();

    float acc[2][4][4] = {};
    uint32_t aOff = (uint32_t)(((wm * 32 + (grp & 1) * 8 + lr) * 136 + (grp >> 1) * 8) * 2);
    uint32_t bOff = (uint32_t)((128 * 136 + (wn * 32 + (grp & 1) * 8 + lr) * 136 + (grp >> 1) * 8) * 2);
#pragma unroll
    for (int k2 = 0; k2 < 128; k2 += 16) {
        uint32_t af[2][4], bf[4][2];
#pragma unroll
        for (int mi = 0; mi < 2; mi++)
            ldsm_x4(af[mi], sbase + aOff + (uint32_t)((mi * 16 * 136 + k2) * 2));
#pragma unroll
        for (int nj = 0; nj < 2; nj++) {
            uint32_t q[4];
            ldsm_x4(q, sbase + bOff + (uint32_t)((nj * 16 * 136 + k2) * 2));
            bf[nj * 2][0] = q[0]; bf[nj * 2 + 1][0] = q[1];
            bf[nj * 2][1] = q[2]; bf[nj * 2 + 1][1] = q[3];
        }
#pragma unroll
        for (int mi = 0; mi < 2; mi++)
#pragma unroll
            for (int ni = 0; ni < 4; ni++)
                mma_f16(acc[mi][ni], af[mi], bf[ni]);
    }

#pragma unroll
    for (int mi = 0; mi < 2; mi++) {
#pragma unroll
        for (int ni = 0; ni < 4; ni++) {
            int n = wn * 32 + ni * 8 + tg * 2;
#pragma unroll
            for (int hf = 0; hf < 2; hf++) {
                int grow = m0 + wm * 32 + mi * 16 + gp + hf * 8;
                int b2 = grow / Cc, c2 = grow % Cc;
                size_t addr = ((size_t)(b2 * Hn + h) * Cc + c2) * 64 + n;
                d_Q[addr]     = acc[mi][ni][hf * 2];
                d_Q[addr + 1] = acc[mi][ni][hf * 2 + 1];
            }
        }
    }
}

// ---------------- stage 2: serial state pass -> Pt2h [h][m][64] fp16 ----------------
__global__ __launch_bounds__(256) void st2_kernel(int layer)
{
    int t = blockIdx.x * 256 + threadIdx.x;   // 131072
    int n = t & 31;
    int bh = t >> 5;
    int h = bh & 255, b = bh >> 8;
    float2 lt = d_lamT[(layer * Hn + h) * 32 + n];
    const float* qp = d_Q + (size_t)bh * (Cc * 64);
    __half* pp = d_Pt2h + ((size_t)h * Mrows + b * Cc) * 64;
    float pr = 0.f, pi = 0.f;
    for (int c = 0; c < Cc; c++) {
        pp[c * 64 + n]      = __float2half_rn(pr);
        pp[c * 64 + 32 + n] = __float2half_rn(pi);
        float qr = qp[c * 64 + n], qi = qp[c * 64 + 32 + n];
        float prn = fmaf(lt.x, pr, fmaf(-lt.y, pi, qr));
        pi        = fmaf(lt.y, pr, fmaf( lt.x, pi, qi));
        pr = prn;
    }
}

// ---- stage 3: y = [u|p] @ B3^T, gelu -> Gt fp16, single-shot resident smem ---------
__global__ __launch_bounds__(256) void st3_kernel(int layer)
{
    extern __shared__ __half smh[];
    __half* As = smh;                      // [128][200] (U 0..127 | P 128..191 | pad)
    __half* Bs = smh + 128 * 200;          // [128][200]
    uint32_t sbase;
    asm("{ .reg .u64 t; cvta.to.shared.u64 t, %1; cvt.u32.u64 %0, t; }" : "=r"(sbase) : "l"(smh));
    int h  = blockIdx.y;
    int m0 = blockIdx.x * 128;
    int tid = threadIdx.x, lane = tid & 31, wid = tid >> 5;
    int wm = wid & 3, wn = wid >> 2;
    int tg = lane & 3, gp = lane >> 2;
    int grp = lane >> 3, lr = lane & 7;

    for (int i = 0; i < 12; i++) {
        int idx = tid + i * 256;
        int r = idx / 24, g = idx - r * 24;
        int gm = m0 + r;
        int bbA = gm / Cc, ccA = gm % Cc;
        const __half* src;
        if (g < 16)
            src = d_Ztr + ((size_t)(bbA * Hn + h)) * LP + ccA * Tc + g * 8;
        else
            src = d_Pt2h + ((size_t)h * Mrows + gm) * 64 + (g - 16) * 8;
        cp16h(As + r * 200 + g * 8, src);
    }
    const __half* B3p = d_B3h + (size_t)(layer * Hn + h) * (128 * 192);
    for (int i = 0; i < 12; i++) {
        int idx = tid + i * 256;
        int r = idx / 24, g = idx - r * 24;
        cp16h(Bs + r * 200 + g * 8, B3p + r * 192 + g * 8);
    }
    cp_commit();
    cp_wait<0>();
    __syncthreads();

    float acc[2][8][4] = {};
    uint32_t aOff = (uint32_t)(((wm * 32 + (grp & 1) * 8 + lr) * 200 + (grp >> 1) * 8) * 2);
    uint32_t bOff = (uint32_t)((128 * 200 + (wn * 64 + (grp & 1) * 8 + lr) * 200 + (grp >> 1) * 8) * 2);
#pragma unroll
    for (int k2 = 0; k2 < 192; k2 += 16) {
        uint32_t af[2][4], bf[8][2];
#pragma unroll
        for (int mi = 0; mi < 2; mi++)
            ldsm_x4(af[mi], sbase + aOff + (uint32_t)((mi * 16 * 200 + k2) * 2));
#pragma unroll
        for (int nj = 0; nj < 4; nj++) {
            uint32_t q[4];
            ldsm_x4(q, sbase + bOff + (uint32_t)((nj * 16 * 200 + k2) * 2));
            bf[nj * 2][0] = q[0]; bf[nj * 2 + 1][0] = q[1];
            bf[nj * 2][1] = q[2]; bf[nj * 2 + 1][1] = q[3];
        }
#pragma unroll
        for (int mi = 0; mi < 2; mi++)
#pragma unroll
            for (int ni = 0; ni < 8; ni++)
                mma_f16(acc[mi][ni], af[mi], bf[ni]);
    }

    __syncthreads();
    __half* stg = smh;                     // [128][136]
#pragma unroll
    for (int mi = 0; mi < 2; mi++) {
#pragma unroll
        for (int ni = 0; ni < 8; ni++) {
            int i = wn * 64 + ni * 8 + tg * 2;
#pragma unroll
            for (int hf = 0; hf < 2; hf++) {
                int ml = wm * 32 + mi * 16 + gp + hf * 8;
                __half2 v = __floats2half2_rn(gelu_fast(acc[mi][ni][hf * 2]),
                                              gelu_fast(acc[mi][ni][hf * 2 + 1]));
                *(__half2*)&stg[ml * 136 + i] = v;
            }
        }
    }
    __syncthreads();
#pragma unroll
    for (int it = 0; it < 8; it++) {
        int idx = tid + it * 256;
        int row = idx >> 4, g = idx & 15;
        int grow = m0 + row;
        int b2 = grow / Cc, c2 = grow % Cc;
        uint4 v = *(const uint4*)&stg[row * 136 + g * 8];
        *(uint4*)(d_Gt + ((size_t)(b2 * Hn + h)) * LP + c2 * Tc + g * 8) = v;
    }
}

// -------- GLU GEMM fp16 (ldmatrix, direct Gt): D[ch 128][l 128] = W2t x Gt^T --------
// Residual staged from Ztr (fp16); output X written fp16.
__global__ __launch_bounds__(256) void glu_kernel(int layer)
{
    extern __shared__ __half smh[];
    __shared__ float biasS[128];
    uint32_t sbase;
    asm("{ .reg .u64 t; cvta.to.shared.u64 t, %1; cvt.u32.u64 %0, t; }" : "=r"(sbase) : "l"(smh));
    const int tile = blockIdx.x;           // channel group 0..3
    const int l0   = blockIdx.y * 128;
    const int b    = blockIdx.z;
    const int m0   = tile * 128;
    int tid = threadIdx.x, lane = tid & 31, wid = tid >> 5;
    int wm = wid & 3, wn = wid >> 2;       // warp tile: 32 m x 64 n
    int tg = lane & 3, gp = lane >> 2;

    if (tid < 128) biasS[tid] = d_b2t[layer * 512 + m0 + tid];

    __half* Zs = smh + 34048;              // [64][136] residual tile

    int rA = tid >> 1, gA = (tid & 1) * 2;
    const __half* Wp = d_W2th + (size_t)(layer * 512 + m0 + rA) * 256;
    int rB = tid >> 3, gB = tid & 7;       // B: 32 k-rows x 16 granules, 2 per thread
    const __half* Gp = d_Gt + ((size_t)(b * Hn + rB)) * LP + l0;

    float acc[2][8][4] = {};

    auto fill = [&](int s) {
        int kt = s * 32;
        __half* dA = smh + (s % 3) * (128 * 40);
        cp16h(dA + rA * 40 + gA * 8, Wp + kt + gA * 8);
        cp16h(dA + rA * 40 + (gA + 1) * 8, Wp + kt + (gA + 1) * 8);
        __half* dB = smh + 15360 + (s % 3) * (32 * 136);
        const __half* src = Gp + (size_t)kt * LP;
        cp16h(dB + rB * 136 + gB * 8, src + gB * 8);
        cp16h(dB + rB * 136 + (gB + 8) * 8, src + (gB + 8) * 8);
    };

    int grp = lane >> 3, lr = lane & 7;
    uint32_t aOff = (uint32_t)(((wm * 32 + (grp & 1) * 8 + lr) * 40 + (grp >> 1) * 8) * 2);
    uint32_t bOff = (uint32_t)((((grp & 1) * 8 + lr) * 136 + wn * 64 + (grp >> 1) * 8) * 2);

    fill(0);
    for (int i = 0; i < 4; i++) {
        int idx = tid + i * 256;
        int r = idx >> 4, g = idx & 15;
        cp16h(Zs + r * 136 + g * 8,
              d_Ztr + ((size_t)(b * Hn + tile * 64 + r)) * LP + l0 + g * 8);
    }
    cp_commit();
    fill(1); cp_commit();
#pragma unroll
    for (int s = 0; s < 8; s++) {
        if (s < 7) cp_wait<1>(); else cp_wait<0>();
        __syncthreads();
        if (s + 2 < 8) { fill(s + 2); cp_commit(); }
        uint32_t aBuf = sbase + (uint32_t)((s % 3) * (128 * 40) * 2);
        uint32_t bBuf = sbase + (uint32_t)((15360 + (s % 3) * (32 * 136)) * 2);
#pragma unroll
        for (int k2 = 0; k2 < 32; k2 += 16) {
            uint32_t af[2][4], bf[8][2];
#pragma unroll
            for (int mi = 0; mi < 2; mi++)
                ldsm_x4(af[mi], aBuf + aOff + (uint32_t)((mi * 16 * 40 + k2) * 2));
#pragma unroll
            for (int nj = 0; nj < 4; nj++) {
                uint32_t q[4];
                ldsm_x4_t(q, bBuf + bOff + (uint32_t)((k2 * 136 + nj * 16) * 2));
                bf[nj * 2][0] = q[0]; bf[nj * 2][1] = q[1];
                bf[nj * 2 + 1][0] = q[2]; bf[nj * 2 + 1][1] = q[3];
            }
#pragma unroll
            for (int mi = 0; mi < 2; mi++)
#pragma unroll
                for (int ni = 0; ni < 8; ni++)
                    mma_f16(acc[mi][ni], af[mi], bf[ni]);
        }
    }

    // stage C[ch][l] (+bias) in fp32, then GLU + fp16 residual from Zs, fp16 X writes
    __syncthreads();
    float* stgF = (float*)smh;             // [128 ch][133 l]
#pragma unroll
    for (int mi = 0; mi < 2; mi++) {
#pragma unroll
        for (int hf = 0; hf < 2; hf++) {
            int row = wm * 32 + mi * 16 + gp + hf * 8;
            float bv = biasS[row];
#pragma unroll
            for (int ni = 0; ni < 8; ni++) {
                int col = wn * 64 + ni * 8 + tg * 2;
                stgF[row * 133 + col]     = acc[mi][ni][hf * 2]     + bv;
                stgF[row * 133 + col + 1] = acc[mi][ni][hf * 2 + 1] + bv;
            }
        }
    }
    __syncthreads();
#pragma unroll
    for (int it = 0; it < 8; it++) {
        int idx = tid + it * 256;          // 2048 tasks = 128 l-rows x 16 quads
        int row_l = idx >> 4;
        int j = (idx & 15) * 4;            // channel within 64
        int gl = l0 + row_l;
        if (gl < Ln) {
            __half* Xp = d_Xh + ((size_t)b * Ln + gl) * Hn + tile * 64;
            float a0 = stgF[(j    ) * 133 + row_l], g0 = stgF[(64 + j    ) * 133 + row_l];
            float a1 = stgF[(j + 1) * 133 + row_l], g1 = stgF[(65 + j    ) * 133 + row_l];
            float a2 = stgF[(j + 2) * 133 + row_l], g2 = stgF[(66 + j    ) * 133 + row_l];
            float a3 = stgF[(j + 3) * 133 + row_l], g3 = stgF[(67 + j    ) * 133 + row_l];
            float4 o;
            o.x = a0 * (1.f / (1.f + __expf(-g0)));
            o.y = a1 * (1.f / (1.f + __expf(-g1)));
            o.z = a2 * (1.f / (1.f + __expf(-g2)));
            o.w = a3 * (1.f / (1.f + __expf(-g3)));
            o.x += __half2float(Zs[(j    ) * 136 + row_l]);
            o.y += __half2float(Zs[(j + 1) * 136 + row_l]);
            o.z += __half2float(Zs[(j + 2) * 136 + row_l]);
            o.w += __half2float(Zs[(j + 3) * 136 + row_l]);
            __half2 p0 = __floats2half2_rn(o.x, o.y);
            __half2 p1 = __floats2half2_rn(o.z, o.w);
            uint2 u;
            u.x = *(uint32_t*)&p0;
            u.y = *(uint32_t*)&p1;
            *(uint2*)(Xp + j) = u;
        }
    }
}

// ---------------- final LayerNorm (fp16 X in) -> d_out ----------------
__global__ __launch_bounds__(256) void final_ln(
    const float* __restrict__ g, const float* __restrict__ bb, float* __restrict__ out)
{
    int lane = threadIdx.x & 31, wid = threadIdx.x >> 5;
    size_t row = (size_t)blockIdx.x * 8 + wid;
    const __half* xr = d_Xh + row * Hn;
    float v[8], s = 0.f, q = 0.f;
#pragma unroll
    for (int k = 0; k < 8; k++) {
        v[k] = __half2float(xr[k * 32 + lane]);
        s += v[k]; q += v[k] * v[k];
    }
#pragma unroll
    for (int o = 16; o; o >>= 1) {
        s += __shfl_xor_sync(0xffffffffu, s, o);
        q += __shfl_xor_sync(0xffffffffu, q, o);
    }
    float m  = s * (1.f / 256.f);
    float sc = rsqrtf(q * (1.f / 256.f) - m * m + 1e-5f);
#pragma unroll
    for (int k = 0; k < 8; k++) {
        int h = k * 32 + lane;
        out[row * Hn + h] = (v[k] - m) * sc * g[h] + bb[h];
    }
}

// ---------------- launch ----------------
extern "C" void kernel_launch(void* const* d_in, const int* in_sizes, int n_in,
                              void* d_out, int out_size)
{
    const float* x       = (const float*)d_in[0];
    const float* W_in    = (const float*)d_in[1];
    const float* b_in    = (const float*)d_in[2];
    const float* ln_g    = (const float*)d_in[3];
    const float* ln_b    = (const float*)d_in[4];
    const float* log_dt  = (const float*)d_in[5];
    const float* logA_re = (const float*)d_in[6];
    const float* A_im    = (const float*)d_in[7];
    const float* Cp      = (const float*)d_in[8];
    const float* Dp      = (const float*)d_in[9];
    const float* W_glu   = (const float*)d_in[10];
    const float* b_glu   = (const float*)d_in[11];
    const float* fn_g    = (const float*)d_in[12];
    const float* fn_b    = (const float*)d_in[13];
    float* out = (float*)d_out;

    const int smem_pow = 8 * 64 * 136 * 2;                    // 139264
    const int smem_st1 = (128 * 136 + 64 * 136) * 2;          // 52224
    const int smem_st3 = (128 * 200 * 2) * 2;                 // 102400
    const int smem_glu = (34048 + 64 * 136) * 2;              // 85504
    cudaFuncSetAttribute(prep_pow, cudaFuncAttributeMaxDynamicSharedMemorySize, smem_pow);
    cudaFuncSetAttribute(st1_kernel, cudaFuncAttributeMaxDynamicSharedMemorySize, smem_st1);
    cudaFuncSetAttribute(st3_kernel, cudaFuncAttributeMaxDynamicSharedMemorySize, smem_st3);
    cudaFuncSetAttribute(glu_kernel, cudaFuncAttributeMaxDynamicSharedMemorySize, smem_glu);

    prep_ssm<<<128, 256>>>(log_dt, logA_re, A_im, Cp);
    prep_pow<<<128, 256, smem_pow>>>();
    prep_tk<<<NLn * Hn, 128>>>(Dp);
    prep_w2t<<<2048, 256>>>(W_glu, b_glu);
    dim3 gln((Ln + 31) / 32, Bn);
    in_proj_ln<<<gln, 256>>>(x, W_in, b_in, ln_g, ln_b);   // layer-0 LN fused

    for (int i = 0; i < NLn; i++) {
        if (i > 0) ln_t_kernel<<<gln, 256>>>(i, ln_g, ln_b);
        st1_kernel<<<dim3(Mrows / 128, Hn), 256, smem_st1>>>(i);
        st2_kernel<<<512, 256>>>(i);
        st3_kernel<<<dim3(Mrows / 128, Hn), 256, smem_st3>>>(i);
        glu_kernel<<<dim3(4, LP / 128, Bn), 256, smem_glu>>>(i);
    }
    final_ln<<<(Bn * Ln) / 8, 256>>>(fn_g, fn_b, out);
}